// round 5
// baseline (speedup 1.0000x reference)
#include <cuda_runtime.h>
#include <math.h>

#define B_    128
#define SDEC  256
#define SENC  256
#define IDIM  256
#define HDIM  512
#define ODIM  256
#define G4H   2048
#define MROWS 32768   // B_*SDEC == B_*SENC

typedef unsigned long long ull;

// ---------------- scratch (device globals; no allocs allowed) ----------------
__device__ float g_xW [(size_t)MROWS * G4H];  // x@W_ih^T + b_ih + b_hh  [b*256+t][col]
__device__ float g_xWt[(size_t)MROWS * G4H];  // transposed: [t][col][b]
__device__ float g_K [(size_t)MROWS * HDIM];  // enc@Wk^T + bk
__device__ float g_V [(size_t)MROWS * HDIM];  // K@Wv^T + bv
__device__ float g_H [(size_t)MROWS * HDIM];  // all h_t  [b*256+t][u]
__device__ float g_Q [(size_t)MROWS * HDIM];  // H@Wq^T + bq
__device__ float g_HC[(size_t)MROWS * HDIM];  // h + context
__device__ float g_S [(size_t)B_ * SDEC * SENC]; // attention probs (32 MB)
__device__ float g_h2[2 * 4 * HDIM * 32];     // h ping-pong  [pp][bg][u][32 b]
__device__ float g_bsum[G4H];
__device__ unsigned g_barc[4];
__device__ unsigned g_barg[4];

__device__ __forceinline__ float sigmoidf_(float x) { return 1.0f / (1.0f + __expf(-x)); }

__device__ __forceinline__ ull ffma2(ull a, ull b, ull c) {
    ull d;
    asm("fma.rn.f32x2 %0, %1, %2, %3;" : "=l"(d) : "l"(a), "l"(b), "l"(c));
    return d;
}
__device__ __forceinline__ ull dup2(float w) {
    unsigned wu = __float_as_uint(w);
    ull w2;
    asm("mov.b64 %0, {%1, %1};" : "=l"(w2) : "r"(wu));
    return w2;
}
__device__ __forceinline__ float lo32(ull v) { return __uint_as_float((unsigned)v); }
__device__ __forceinline__ float hi32(ull v) { return __uint_as_float((unsigned)(v >> 32)); }

// barrier among the 32 blocks of one bg group (pure spin)
__device__ __forceinline__ void bar_bg(int bg, int tid) {
    if (tid == 0) {
        __threadfence();
        volatile unsigned* genp = &g_barg[bg];
        unsigned g = *genp;
        if (atomicAdd(&g_barc[bg], 1) == 31) {
            g_barc[bg] = 0;
            __threadfence();
            atomicExch((unsigned*)&g_barg[bg], g + 1);
        } else {
            while (*genp == g) { }
        }
        __threadfence();
    }
    __syncthreads();
}

// ---------------- bias sum ----------------
__global__ void bias_sum_kernel(const float* __restrict__ b_ih, const float* __restrict__ b_hh) {
    int i = blockIdx.x * 256 + threadIdx.x;
    if (i < G4H) g_bsum[i] = b_ih[i] + b_hh[i];
}

// ---------------- xW transpose: [b*256+t][col] -> [t][col][b] ----------------
__global__ __launch_bounds__(256) void xw_transpose() {
    __shared__ float tile[32][129];
    const int t  = blockIdx.y;
    const int c0 = blockIdx.x * 32;
    const int tid = threadIdx.x;
    const int rc = tid & 31, rb = tid >> 5;
#pragma unroll
    for (int p = 0; p < 16; p++) {
        int b = rb + p * 8;
        tile[rc][b] = g_xW[((size_t)b * SDEC + t) * G4H + c0 + rc];
    }
    __syncthreads();
    const int wb = tid & 127, wc = tid >> 7;
#pragma unroll
    for (int p = 0; p < 16; p++) {
        int c = wc + p * 2;
        g_xWt[((size_t)t * G4H + c0 + c) * B_ + wb] = tile[c][wb];
    }
}

// ---------------- NT SGEMM (f32x2, double-buffered) ----------------
// C[m,n] = alpha * sum_k A[m,k]*B[n,k] + bias[n]. m packed in f32x2 lane pairs;
// B duplicated into smem at store time so no per-FMA dup movs.
__global__ __launch_bounds__(256) void sgemm_nt(
    const float* __restrict__ A, const float* __restrict__ B,
    const float* __restrict__ bias, float* __restrict__ C,
    int M, int N, int K, float alpha,
    size_t sA, size_t sB, size_t sC)
{
    __shared__ __align__(16) float As [2][8][128];
    __shared__ __align__(16) float Bsd[2][8][256];

    const int z = blockIdx.z;
    A += (size_t)z * sA; B += (size_t)z * sB; C += (size_t)z * sC;

    const int tid = threadIdx.x;
    const int m0 = blockIdx.y * 128, n0 = blockIdx.x * 128;
    const int lr = tid >> 1;
    const int lc = (tid & 1) * 4;
    const float* Ag = A + (size_t)(m0 + lr) * K + lc;
    const float* Bg = B + (size_t)(n0 + lr) * K + lc;
    const int tx = tid & 15, ty = tid >> 4;

    ull acc[4][8];
#pragma unroll
    for (int i = 0; i < 4; i++)
#pragma unroll
        for (int j = 0; j < 8; j++) acc[i][j] = 0ull;

    // preload tile 0
    {
        float4 a = *(const float4*)(Ag);
        float4 b = *(const float4*)(Bg);
        As[0][lc + 0][lr] = a.x; As[0][lc + 1][lr] = a.y;
        As[0][lc + 2][lr] = a.z; As[0][lc + 3][lr] = a.w;
        *(float2*)&Bsd[0][lc + 0][2 * lr] = make_float2(b.x, b.x);
        *(float2*)&Bsd[0][lc + 1][2 * lr] = make_float2(b.y, b.y);
        *(float2*)&Bsd[0][lc + 2][2 * lr] = make_float2(b.z, b.z);
        *(float2*)&Bsd[0][lc + 3][2 * lr] = make_float2(b.w, b.w);
    }
    __syncthreads();

    const int KT = K >> 3;
    for (int kt = 0; kt < KT; kt++) {
        const int cur = kt & 1;
        float4 an, bn;
        const bool has = (kt + 1 < KT);
        if (has) {
            an = *(const float4*)(Ag + (kt + 1) * 8);
            bn = *(const float4*)(Bg + (kt + 1) * 8);
        }
#pragma unroll
        for (int kk = 0; kk < 8; kk++) {
            ulonglong2 am01 = *(const ulonglong2*)&As[cur][kk][ty * 8];
            ulonglong2 am23 = *(const ulonglong2*)&As[cur][kk][ty * 8 + 4];
            ulonglong2 b01 = *(const ulonglong2*)&Bsd[cur][kk][tx * 16];
            ulonglong2 b23 = *(const ulonglong2*)&Bsd[cur][kk][tx * 16 + 4];
            ulonglong2 b45 = *(const ulonglong2*)&Bsd[cur][kk][tx * 16 + 8];
            ulonglong2 b67 = *(const ulonglong2*)&Bsd[cur][kk][tx * 16 + 12];
            ull am[4] = {am01.x, am01.y, am23.x, am23.y};
            ull bd[8] = {b01.x, b01.y, b23.x, b23.y, b45.x, b45.y, b67.x, b67.y};
#pragma unroll
            for (int i = 0; i < 4; i++)
#pragma unroll
                for (int j = 0; j < 8; j++)
                    acc[i][j] = ffma2(am[i], bd[j], acc[i][j]);
        }
        if (has) {
            const int nxt = cur ^ 1;
            As[nxt][lc + 0][lr] = an.x; As[nxt][lc + 1][lr] = an.y;
            As[nxt][lc + 2][lr] = an.z; As[nxt][lc + 3][lr] = an.w;
            *(float2*)&Bsd[nxt][lc + 0][2 * lr] = make_float2(bn.x, bn.x);
            *(float2*)&Bsd[nxt][lc + 1][2 * lr] = make_float2(bn.y, bn.y);
            *(float2*)&Bsd[nxt][lc + 2][2 * lr] = make_float2(bn.z, bn.z);
            *(float2*)&Bsd[nxt][lc + 3][2 * lr] = make_float2(bn.w, bn.w);
            __syncthreads();
        }
    }

    float bv0[8];
#pragma unroll
    for (int j = 0; j < 8; j++) bv0[j] = bias ? bias[n0 + tx * 8 + j] : 0.f;

#pragma unroll
    for (int i = 0; i < 4; i++) {
        const int mlo = m0 + ty * 8 + 2 * i;
        float4 o0, o1;
        o0.x = alpha * lo32(acc[i][0]) + bv0[0]; o0.y = alpha * lo32(acc[i][1]) + bv0[1];
        o0.z = alpha * lo32(acc[i][2]) + bv0[2]; o0.w = alpha * lo32(acc[i][3]) + bv0[3];
        o1.x = alpha * lo32(acc[i][4]) + bv0[4]; o1.y = alpha * lo32(acc[i][5]) + bv0[5];
        o1.z = alpha * lo32(acc[i][6]) + bv0[6]; o1.w = alpha * lo32(acc[i][7]) + bv0[7];
        *(float4*)(C + (size_t)mlo * N + n0 + tx * 8)     = o0;
        *(float4*)(C + (size_t)mlo * N + n0 + tx * 8 + 4) = o1;
        float4 p0, p1;
        p0.x = alpha * hi32(acc[i][0]) + bv0[0]; p0.y = alpha * hi32(acc[i][1]) + bv0[1];
        p0.z = alpha * hi32(acc[i][2]) + bv0[2]; p0.w = alpha * hi32(acc[i][3]) + bv0[3];
        p1.x = alpha * hi32(acc[i][4]) + bv0[4]; p1.y = alpha * hi32(acc[i][5]) + bv0[5];
        p1.z = alpha * hi32(acc[i][6]) + bv0[6]; p1.w = alpha * hi32(acc[i][7]) + bv0[7];
        *(float4*)(C + (size_t)(mlo + 1) * N + n0 + tx * 8)     = p0;
        *(float4*)(C + (size_t)(mlo + 1) * N + n0 + tx * 8 + 4) = p1;
    }
}

// ---------------- NN SGEMM + elementwise add: C = A*B + E (batched, f32x2) ----
__global__ __launch_bounds__(256) void sgemm_nn_addE(
    const float* __restrict__ A, const float* __restrict__ B,
    const float* __restrict__ E, float* __restrict__ C,
    int M, int N, int K,
    size_t sA, size_t sB, size_t sE, size_t sC)
{
    __shared__ __align__(16) float As [8][128];
    __shared__ __align__(16) float Bsd[8][256];

    const int z = blockIdx.z;
    A += (size_t)z * sA; B += (size_t)z * sB; E += (size_t)z * sE; C += (size_t)z * sC;

    const int tid = threadIdx.x;
    const int m0 = blockIdx.y * 128, n0 = blockIdx.x * 128;
    const int lr = tid >> 1;
    const int lc = (tid & 1) * 4;
    const float* Ag = A + (size_t)(m0 + lr) * K + lc;
    const int lrB = tid >> 5;
    const int lcB = (tid & 31) * 4;
    const int tx = tid & 15, ty = tid >> 4;

    ull acc[4][8];
#pragma unroll
    for (int i = 0; i < 4; i++)
#pragma unroll
        for (int j = 0; j < 8; j++) acc[i][j] = 0ull;

    for (int k0 = 0; k0 < K; k0 += 8) {
        float4 a = *(const float4*)(Ag + k0);
        float4 b = *(const float4*)(B + (size_t)(k0 + lrB) * N + n0 + lcB);
        __syncthreads();
        As[lc + 0][lr] = a.x; As[lc + 1][lr] = a.y;
        As[lc + 2][lr] = a.z; As[lc + 3][lr] = a.w;
        *(float2*)&Bsd[lrB][2 * (lcB + 0)] = make_float2(b.x, b.x);
        *(float2*)&Bsd[lrB][2 * (lcB + 1)] = make_float2(b.y, b.y);
        *(float2*)&Bsd[lrB][2 * (lcB + 2)] = make_float2(b.z, b.z);
        *(float2*)&Bsd[lrB][2 * (lcB + 3)] = make_float2(b.w, b.w);
        __syncthreads();
#pragma unroll
        for (int kk = 0; kk < 8; kk++) {
            ulonglong2 am01 = *(const ulonglong2*)&As[kk][ty * 8];
            ulonglong2 am23 = *(const ulonglong2*)&As[kk][ty * 8 + 4];
            ulonglong2 b01 = *(const ulonglong2*)&Bsd[kk][tx * 16];
            ulonglong2 b23 = *(const ulonglong2*)&Bsd[kk][tx * 16 + 4];
            ulonglong2 b45 = *(const ulonglong2*)&Bsd[kk][tx * 16 + 8];
            ulonglong2 b67 = *(const ulonglong2*)&Bsd[kk][tx * 16 + 12];
            ull am[4] = {am01.x, am01.y, am23.x, am23.y};
            ull bd[8] = {b01.x, b01.y, b23.x, b23.y, b45.x, b45.y, b67.x, b67.y};
#pragma unroll
            for (int i = 0; i < 4; i++)
#pragma unroll
                for (int j = 0; j < 8; j++)
                    acc[i][j] = ffma2(am[i], bd[j], acc[i][j]);
        }
    }

#pragma unroll
    for (int i = 0; i < 4; i++) {
        const int mlo = m0 + ty * 8 + 2 * i;
        size_t offL = (size_t)mlo * N + n0 + tx * 8;
        size_t offH = (size_t)(mlo + 1) * N + n0 + tx * 8;
        float4 e0 = *(const float4*)(E + offL);
        float4 e1 = *(const float4*)(E + offL + 4);
        float4 f0 = *(const float4*)(E + offH);
        float4 f1 = *(const float4*)(E + offH + 4);
        float4 o0, o1, p0, p1;
        o0.x = lo32(acc[i][0]) + e0.x; o0.y = lo32(acc[i][1]) + e0.y;
        o0.z = lo32(acc[i][2]) + e0.z; o0.w = lo32(acc[i][3]) + e0.w;
        o1.x = lo32(acc[i][4]) + e1.x; o1.y = lo32(acc[i][5]) + e1.y;
        o1.z = lo32(acc[i][6]) + e1.z; o1.w = lo32(acc[i][7]) + e1.w;
        p0.x = hi32(acc[i][0]) + f0.x; p0.y = hi32(acc[i][1]) + f0.y;
        p0.z = hi32(acc[i][2]) + f0.z; p0.w = hi32(acc[i][3]) + f0.w;
        p1.x = hi32(acc[i][4]) + f1.x; p1.y = hi32(acc[i][5]) + f1.y;
        p1.z = hi32(acc[i][6]) + f1.z; p1.w = hi32(acc[i][7]) + f1.w;
        *(float4*)(C + offL)     = o0;
        *(float4*)(C + offL + 4) = o1;
        *(float4*)(C + offH)     = p0;
        *(float4*)(C + offH + 4) = p1;
    }
}

// ---------------- persistent LSTM v3 ----------------
// 128 blocks = 4 bg x 32 us. 128 threads: thread = (iu2: unit-pair, bp: batch-pair).
// 8 FFMA2/k/thread = 32 MACs. ws 128 KB + hs 64 KB smem. c in registers.
#define WS_FLOATS (HDIM * 64)
#define HS_FLOATS (HDIM * 32)
__global__ __launch_bounds__(128, 1) void lstm_persistent3(const float* __restrict__ W_hh)
{
    extern __shared__ float sm[];
    float* ws = sm;                 // [k][64] : r = iu*4 + gate
    float* hs = sm + WS_FLOATS;     // [k][32 local b]

    const int tid = threadIdx.x;
    const int bg = blockIdx.x >> 5;
    const int us = blockIdx.x & 31;
    const int iu2 = tid >> 4;             // 0..7 unit-pair
    const int bp  = tid & 15;             // 0..15 batch-pair
    const int bl  = bp * 2;
    const int b0  = bg * 32 + bl;
    const int ugl = us * 16 + iu2 * 2;    // global unit base (2 units)

    // one-time: stage W_hh slice into smem
    {
        const int r = tid >> 1;           // 0..63
        const int iu_r = r >> 2, g_r = r & 3;
        const size_t grow = ((size_t)(g_r * HDIM + us * 16 + iu_r)) * HDIM;
        for (int k = (tid & 1) * 4; k < HDIM; k += 8) {
            float4 w = *(const float4*)(W_hh + grow + k);
            ws[(k + 0) * 64 + r] = w.x;
            ws[(k + 1) * 64 + r] = w.y;
            ws[(k + 2) * 64 + r] = w.z;
            ws[(k + 3) * 64 + r] = w.w;
        }
    }

    // one-time: zero our slice of h0
    for (int idx = tid; idx < 16 * 32; idx += 128)
        g_h2[bg * (HDIM * 32) + (us * 16 + (idx >> 5)) * 32 + (idx & 31)] = 0.f;

    float cc[2][2] = {{0.f, 0.f}, {0.f, 0.f}};

    __syncthreads();
    bar_bg(bg, tid);

    const float* wp = ws + iu2 * 8;
    const float* hp = hs + bl;

    for (int t = 0; t < SDEC; t++) {
        const int cur = t & 1, nxt = cur ^ 1;

        // prefetch x-part of gates [gate][unit] as float2 over (b0,b0+1)
        float2 xg[4][2];
        {
            const size_t xoff = (size_t)t * (G4H * B_) + (size_t)bg * 32 + bl;
#pragma unroll
            for (int g = 0; g < 4; g++)
#pragma unroll
                for (int u = 0; u < 2; u++)
                    xg[g][u] = *(const float2*)&g_xWt[xoff + (size_t)(g * HDIM + ugl + u) * B_];
        }

        // bulk-load this bg's h slice [512][32] into smem (L2-only)
        const float* hsrc = g_h2 + cur * (4 * HDIM * 32) + bg * (HDIM * 32);
        for (int i = tid * 4; i < HS_FLOATS; i += 512) {
            float4 v = __ldcg((const float4*)(hsrc + i));
            *(float4*)&hs[i] = v;
        }
        __syncthreads();

        // pure-smem GEMM: 2 units x 4 gates x 2 batch, gate-pairs in f32x2 lanes
        ull aif0a = 0, ago0a = 0, aif1a = 0, ago1a = 0;
        ull aif0b = 0, ago0b = 0, aif1b = 0, ago1b = 0;
#pragma unroll 8
        for (int k = 0; k < HDIM; k++) {
            ulonglong2 wa = *(const ulonglong2*)(wp + k * 64);       // unit a: (i,f),(g,o)
            ulonglong2 wb = *(const ulonglong2*)(wp + k * 64 + 4);   // unit b
            float2 hv = *(const float2*)(hp + k * 32);
            ull ha = dup2(hv.x);
            ull hb = dup2(hv.y);
            aif0a = ffma2(wa.x, ha, aif0a);
            ago0a = ffma2(wa.y, ha, ago0a);
            aif1a = ffma2(wb.x, ha, aif1a);
            ago1a = ffma2(wb.y, ha, ago1a);
            aif0b = ffma2(wa.x, hb, aif0b);
            ago0b = ffma2(wa.y, hb, ago0b);
            aif1b = ffma2(wb.x, hb, aif1b);
            ago1b = ffma2(wb.y, hb, ago1b);
        }

        // gates = h-part + x-part; cell + hidden update in registers
        float h[2][2];
        {
            float iv, fv, gv, ov, c;
            // unit 0, b0
            iv = lo32(aif0a) + xg[0][0].x; fv = hi32(aif0a) + xg[1][0].x;
            gv = lo32(ago0a) + xg[2][0].x; ov = hi32(ago0a) + xg[3][0].x;
            c = sigmoidf_(fv) * cc[0][0] + sigmoidf_(iv) * tanhf(gv);
            cc[0][0] = c; h[0][0] = sigmoidf_(ov) * tanhf(c);
            // unit 1, b0
            iv = lo32(aif1a) + xg[0][1].x; fv = hi32(aif1a) + xg[1][1].x;
            gv = lo32(ago1a) + xg[2][1].x; ov = hi32(ago1a) + xg[3][1].x;
            c = sigmoidf_(fv) * cc[1][0] + sigmoidf_(iv) * tanhf(gv);
            cc[1][0] = c; h[1][0] = sigmoidf_(ov) * tanhf(c);
            // unit 0, b1
            iv = lo32(aif0b) + xg[0][0].y; fv = hi32(aif0b) + xg[1][0].y;
            gv = lo32(ago0b) + xg[2][0].y; ov = hi32(ago0b) + xg[3][0].y;
            c = sigmoidf_(fv) * cc[0][1] + sigmoidf_(iv) * tanhf(gv);
            cc[0][1] = c; h[0][1] = sigmoidf_(ov) * tanhf(c);
            // unit 1, b1
            iv = lo32(aif1b) + xg[0][1].y; fv = hi32(aif1b) + xg[1][1].y;
            gv = lo32(ago1b) + xg[2][1].y; ov = hi32(ago1b) + xg[3][1].y;
            c = sigmoidf_(fv) * cc[1][1] + sigmoidf_(iv) * tanhf(gv);
            cc[1][1] = c; h[1][1] = sigmoidf_(ov) * tanhf(c);
        }

        // publish h
        float* hdst = g_h2 + nxt * (4 * HDIM * 32) + bg * (HDIM * 32);
        *(float2*)&hdst[(ugl + 0) * 32 + bl] = make_float2(h[0][0], h[0][1]);
        *(float2*)&hdst[(ugl + 1) * 32 + bl] = make_float2(h[1][0], h[1][1]);
        *(float2*)&g_H[((size_t)b0 * SDEC + t) * HDIM + ugl]       = make_float2(h[0][0], h[1][0]);
        *(float2*)&g_H[((size_t)(b0 + 1) * SDEC + t) * HDIM + ugl] = make_float2(h[0][1], h[1][1]);

        __syncthreads();
        bar_bg(bg, tid);
    }
}

// ---------------- softmax over last dim (256) ----------------
__global__ __launch_bounds__(256) void softmax256(float* __restrict__ S) {
    __shared__ float red[256];
    const int t = threadIdx.x;
    float* p = S + (size_t)blockIdx.x * SENC;
    float v = p[t];
    red[t] = v; __syncthreads();
    for (int s = 128; s > 0; s >>= 1) { if (t < s) red[t] = fmaxf(red[t], red[t + s]); __syncthreads(); }
    float mx = red[0]; __syncthreads();
    float e = __expf(v - mx);
    red[t] = e; __syncthreads();
    for (int s = 128; s > 0; s >>= 1) { if (t < s) red[t] += red[t + s]; __syncthreads(); }
    p[t] = e * (1.0f / red[0]);
}

// ---------------- host ----------------
extern "C" void kernel_launch(void* const* d_in, const int* in_sizes, int n_in,
                              void* d_out, int out_size) {
    const float* x    = (const float*)d_in[0];
    const float* enc  = (const float*)d_in[1];
    const float* W_ih = (const float*)d_in[2];
    const float* W_hh = (const float*)d_in[3];
    const float* b_ih = (const float*)d_in[4];
    const float* b_hh = (const float*)d_in[5];
    const float* Wq   = (const float*)d_in[6];
    const float* bq   = (const float*)d_in[7];
    const float* Wk   = (const float*)d_in[8];
    const float* bk   = (const float*)d_in[9];
    const float* Wv   = (const float*)d_in[10];
    const float* bv   = (const float*)d_in[11];
    const float* Wfc  = (const float*)d_in[12];
    const float* bfc  = (const float*)d_in[13];
    float* out = (float*)d_out;

    float *p_xW, *p_K, *p_V, *p_H, *p_Q, *p_HC, *p_S, *p_bsum;
    cudaGetSymbolAddress((void**)&p_xW,  g_xW);
    cudaGetSymbolAddress((void**)&p_K,   g_K);
    cudaGetSymbolAddress((void**)&p_V,   g_V);
    cudaGetSymbolAddress((void**)&p_H,   g_H);
    cudaGetSymbolAddress((void**)&p_Q,   g_Q);
    cudaGetSymbolAddress((void**)&p_HC,  g_HC);
    cudaGetSymbolAddress((void**)&p_S,   g_S);
    cudaGetSymbolAddress((void**)&p_bsum,g_bsum);

    const float scale = 1.0f / sqrtf((float)HDIM);

    cudaFuncSetAttribute(lstm_persistent3,
                         cudaFuncAttributeMaxDynamicSharedMemorySize,
                         (WS_FLOATS + HS_FLOATS) * sizeof(float));

    bias_sum_kernel<<<G4H / 256, 256>>>(b_ih, b_hh);

    // xW = x @ W_ih^T + (b_ih + b_hh)      [32768 x 2048], K=256
    sgemm_nt<<<dim3(G4H / 128, MROWS / 128, 1), 256>>>(
        x, W_ih, p_bsum, p_xW, MROWS, G4H, IDIM, 1.0f, 0, 0, 0);
    // permute to [t][col][b]
    xw_transpose<<<dim3(G4H / 32, SDEC), 256>>>();
    // K = enc @ Wk^T + bk
    sgemm_nt<<<dim3(HDIM / 128, MROWS / 128, 1), 256>>>(
        enc, Wk, bk, p_K, MROWS, HDIM, HDIM, 1.0f, 0, 0, 0);
    // V = K @ Wv^T + bv
    sgemm_nt<<<dim3(HDIM / 128, MROWS / 128, 1), 256>>>(
        p_K, Wv, bv, p_V, MROWS, HDIM, HDIM, 1.0f, 0, 0, 0);

    // entire sequential LSTM in one persistent launch
    lstm_persistent3<<<128, 128, (WS_FLOATS + HS_FLOATS) * sizeof(float)>>>(W_hh);

    // Q = H @ Wq^T + bq
    sgemm_nt<<<dim3(HDIM / 128, MROWS / 128, 1), 256>>>(
        p_H, Wq, bq, p_Q, MROWS, HDIM, HDIM, 1.0f, 0, 0, 0);

    // scores: per-batch S[t,s] = scale * Q[t,:]·K[s,:]
    sgemm_nt<<<dim3(SENC / 128, SDEC / 128, B_), 256>>>(
        p_Q, p_K, nullptr, p_S, SDEC, SENC, HDIM, scale,
        (size_t)SDEC * HDIM, (size_t)SENC * HDIM, (size_t)SDEC * SENC);

    softmax256<<<B_ * SDEC, 256>>>(p_S);

    // context + h: HC[t,h] = sum_s S[t,s] * V[s,h] + H[t,h]
    sgemm_nn_addE<<<dim3(HDIM / 128, SDEC / 128, B_), 256>>>(
        p_S, p_V, p_H, p_HC, SDEC, HDIM, SENC,
        (size_t)SDEC * SENC, (size_t)SENC * HDIM,
        (size_t)SDEC * HDIM, (size_t)SDEC * HDIM);

    // out = HC @ Wfc^T + bfc               [32768 x 256]
    sgemm_nt<<<dim3(ODIM / 128, MROWS / 128, 1), 256>>>(
        p_HC, Wfc, bfc, out, MROWS, ODIM, HDIM, 1.0f, 0, 0, 0);
}

// round 6
// speedup vs baseline: 2.1198x; 2.1198x over previous
#include <cuda_runtime.h>
#include <math.h>

#define B_    128
#define SDEC  256
#define SENC  256
#define IDIM  256
#define HDIM  512
#define ODIM  256
#define G4H   2048
#define MROWS 32768   // B_*SDEC == B_*SENC

typedef unsigned long long ull;
typedef unsigned int u32;

// ---------------- scratch (device globals; no allocs allowed) ----------------
__device__ float g_xWt[(size_t)MROWS * G4H];  // x@W_ih^T + biases, layout [t][b][col]
__device__ float g_K [(size_t)MROWS * HDIM];  // enc@Wk^T + bk
__device__ float g_V [(size_t)MROWS * HDIM];  // K@Wv^T + bv
__device__ float g_H [(size_t)MROWS * HDIM];  // all h_t  [b*256+t][u]
__device__ float g_Q [(size_t)MROWS * HDIM];  // H@Wq^T + bq
__device__ float g_HC[(size_t)MROWS * HDIM];  // h + context
__device__ float g_S [(size_t)B_ * SDEC * SENC]; // attention probs
__device__ float g_h2[2 * 4 * HDIM * 32];     // h ping-pong [pp][bg][u][32 b]
__device__ float g_bsum[G4H];
__device__ unsigned g_barc[4];
__device__ unsigned g_barg[4];

__device__ __forceinline__ float sigmoidf_(float x) { return 1.0f / (1.0f + __expf(-x)); }

__device__ __forceinline__ ull ffma2(ull a, ull b, ull c) {
    ull d;
    asm("fma.rn.f32x2 %0, %1, %2, %3;" : "=l"(d) : "l"(a), "l"(b), "l"(c));
    return d;
}
__device__ __forceinline__ ull dup2(float w) {
    unsigned wu = __float_as_uint(w);
    ull w2;
    asm("mov.b64 %0, {%1, %1};" : "=l"(w2) : "r"(wu));
    return w2;
}
__device__ __forceinline__ float lo32(ull v) { return __uint_as_float((unsigned)v); }
__device__ __forceinline__ float hi32(ull v) { return __uint_as_float((unsigned)(v >> 32)); }

__device__ __forceinline__ float totf32(float x) {
    u32 r;
    asm("cvt.rna.tf32.f32 %0, %1;" : "=r"(r) : "f"(x));
    return __uint_as_float(r);
}
__device__ __forceinline__ void mma_tf32(float* c, const u32* a, const u32* b) {
    asm("mma.sync.aligned.m16n8k8.row.col.f32.tf32.tf32.f32 "
        "{%0,%1,%2,%3},{%4,%5,%6,%7},{%8,%9},{%0,%1,%2,%3};"
        : "+f"(c[0]), "+f"(c[1]), "+f"(c[2]), "+f"(c[3])
        : "r"(a[0]), "r"(a[1]), "r"(a[2]), "r"(a[3]), "r"(b[0]), "r"(b[1]));
}

// ---------------- bias sum ----------------
__global__ void bias_sum_kernel(const float* __restrict__ b_ih, const float* __restrict__ b_hh) {
    int i = blockIdx.x * 256 + threadIdx.x;
    if (i < G4H) g_bsum[i] = b_ih[i] + b_hh[i];
}

// ================= TF32 NT GEMM =================
// C[m,n] = alpha * sum_k A[m,k]*B[n,k] + bias[n].  A [M,K] rm, B [N,K] rm.
// 128x128 CTA tile, 8 warps (64x32 warp tile), k-tile 16, double buffered.
// xwmode: write C at [(t*128+b)*N + n] with m = b*256+t (fused transpose).
#define KTILE 16
__global__ __launch_bounds__(256) void gemm_nt_tf32(
    const float* __restrict__ A, const float* __restrict__ B,
    const float* __restrict__ bias, float* __restrict__ C,
    int M, int N, int K, float alpha,
    size_t sA, size_t sB, size_t sC, int xwmode)
{
    __shared__ float As[2][KTILE][136];
    __shared__ float Bs[2][KTILE][136];

    const int z = blockIdx.z;
    A += (size_t)z * sA; B += (size_t)z * sB; C += (size_t)z * sC;

    const int tid = threadIdx.x;
    const int m0 = blockIdx.y * 128, n0 = blockIdx.x * 128;
    const int w = tid >> 5, lane = tid & 31;
    const int wm = (w >> 2) * 64, wn = (w & 3) * 32;
    const int gq = lane >> 2, tg = lane & 3;

    const int lm = tid & 127;
    const int lk = (tid >> 7) * 8;
    const float* Ag = A + (size_t)(m0 + lm) * K + lk;
    const float* Bg = B + (size_t)(n0 + lm) * K + lk;

    float acc[16][4];
#pragma unroll
    for (int i = 0; i < 16; i++)
#pragma unroll
        for (int j = 0; j < 4; j++) acc[i][j] = 0.f;

    // preload tile 0
    float4 pa0 = *(const float4*)(Ag);
    float4 pa1 = *(const float4*)(Ag + 4);
    float4 pb0 = *(const float4*)(Bg);
    float4 pb1 = *(const float4*)(Bg + 4);
    {
        As[0][lk + 0][lm] = totf32(pa0.x); As[0][lk + 1][lm] = totf32(pa0.y);
        As[0][lk + 2][lm] = totf32(pa0.z); As[0][lk + 3][lm] = totf32(pa0.w);
        As[0][lk + 4][lm] = totf32(pa1.x); As[0][lk + 5][lm] = totf32(pa1.y);
        As[0][lk + 6][lm] = totf32(pa1.z); As[0][lk + 7][lm] = totf32(pa1.w);
        Bs[0][lk + 0][lm] = totf32(pb0.x); Bs[0][lk + 1][lm] = totf32(pb0.y);
        Bs[0][lk + 2][lm] = totf32(pb0.z); Bs[0][lk + 3][lm] = totf32(pb0.w);
        Bs[0][lk + 4][lm] = totf32(pb1.x); Bs[0][lk + 5][lm] = totf32(pb1.y);
        Bs[0][lk + 6][lm] = totf32(pb1.z); Bs[0][lk + 7][lm] = totf32(pb1.w);
    }
    __syncthreads();

    const int KTiles = K / KTILE;
    for (int kt = 0; kt < KTiles; kt++) {
        const int cur = kt & 1;
        const bool has = (kt + 1 < KTiles);
        if (has) {
            pa0 = *(const float4*)(Ag + (kt + 1) * KTILE);
            pa1 = *(const float4*)(Ag + (kt + 1) * KTILE + 4);
            pb0 = *(const float4*)(Bg + (kt + 1) * KTILE);
            pb1 = *(const float4*)(Bg + (kt + 1) * KTILE + 4);
        }
#pragma unroll
        for (int kk = 0; kk < 2; kk++) {
            const int kb = kk * 8;
            u32 af[4][4], bf[4][2];
#pragma unroll
            for (int mi = 0; mi < 4; mi++) {
                af[mi][0] = __float_as_uint(As[cur][kb + tg    ][wm + mi * 16 + gq]);
                af[mi][1] = __float_as_uint(As[cur][kb + tg    ][wm + mi * 16 + gq + 8]);
                af[mi][2] = __float_as_uint(As[cur][kb + tg + 4][wm + mi * 16 + gq]);
                af[mi][3] = __float_as_uint(As[cur][kb + tg + 4][wm + mi * 16 + gq + 8]);
            }
#pragma unroll
            for (int ni = 0; ni < 4; ni++) {
                bf[ni][0] = __float_as_uint(Bs[cur][kb + tg    ][wn + ni * 8 + gq]);
                bf[ni][1] = __float_as_uint(Bs[cur][kb + tg + 4][wn + ni * 8 + gq]);
            }
#pragma unroll
            for (int mi = 0; mi < 4; mi++)
#pragma unroll
                for (int ni = 0; ni < 4; ni++)
                    mma_tf32(acc[mi * 4 + ni], af[mi], bf[ni]);
        }
        if (has) {
            const int nb = cur ^ 1;
            As[nb][lk + 0][lm] = totf32(pa0.x); As[nb][lk + 1][lm] = totf32(pa0.y);
            As[nb][lk + 2][lm] = totf32(pa0.z); As[nb][lk + 3][lm] = totf32(pa0.w);
            As[nb][lk + 4][lm] = totf32(pa1.x); As[nb][lk + 5][lm] = totf32(pa1.y);
            As[nb][lk + 6][lm] = totf32(pa1.z); As[nb][lk + 7][lm] = totf32(pa1.w);
            Bs[nb][lk + 0][lm] = totf32(pb0.x); Bs[nb][lk + 1][lm] = totf32(pb0.y);
            Bs[nb][lk + 2][lm] = totf32(pb0.z); Bs[nb][lk + 3][lm] = totf32(pb0.w);
            Bs[nb][lk + 4][lm] = totf32(pb1.x); Bs[nb][lk + 5][lm] = totf32(pb1.y);
            Bs[nb][lk + 6][lm] = totf32(pb1.z); Bs[nb][lk + 7][lm] = totf32(pb1.w);
            __syncthreads();
        }
    }

#pragma unroll
    for (int ni = 0; ni < 4; ni++) {
        const int ncol = n0 + wn + ni * 8 + tg * 2;
        float2 bv = make_float2(0.f, 0.f);
        if (bias) bv = *(const float2*)&bias[ncol];
#pragma unroll
        for (int mi = 0; mi < 4; mi++) {
            const float* c = acc[mi * 4 + ni];
            const int mr0 = m0 + wm + mi * 16 + gq;
            float2 lo = make_float2(alpha * c[0] + bv.x, alpha * c[1] + bv.y);
            float2 hi = make_float2(alpha * c[2] + bv.x, alpha * c[3] + bv.y);
            if (xwmode) {
                const int bb = mr0 >> 8, t0 = mr0 & 255;
                *(float2*)&C[((size_t)t0 * B_ + bb) * N + ncol]       = lo;
                *(float2*)&C[((size_t)(t0 + 8) * B_ + bb) * N + ncol] = hi;
            } else {
                *(float2*)&C[(size_t)mr0 * N + ncol]       = lo;
                *(float2*)&C[(size_t)(mr0 + 8) * N + ncol] = hi;
            }
        }
    }
}

// ================= TF32 NN GEMM + E add =================
// C[m,n] = sum_k A[m,k]*B[k,n] + E[m,n].  A [M,K] rm, B [K,N] rm. Batched via z.
__global__ __launch_bounds__(256) void gemm_nn_addE_tf32(
    const float* __restrict__ A, const float* __restrict__ B,
    const float* __restrict__ E, float* __restrict__ C,
    int M, int N, int K,
    size_t sA, size_t sB, size_t sE, size_t sC)
{
    __shared__ float As[2][KTILE][136];
    __shared__ float Bs[2][KTILE][136];

    const int z = blockIdx.z;
    A += (size_t)z * sA; B += (size_t)z * sB; E += (size_t)z * sE; C += (size_t)z * sC;

    const int tid = threadIdx.x;
    const int m0 = blockIdx.y * 128, n0 = blockIdx.x * 128;
    const int w = tid >> 5, lane = tid & 31;
    const int wm = (w >> 2) * 64, wn = (w & 3) * 32;
    const int gq = lane >> 2, tg = lane & 3;

    const int lm = tid & 127;
    const int lk = (tid >> 7) * 8;
    const float* Ag = A + (size_t)(m0 + lm) * K + lk;
    const int ln  = lane * 4;       // 0..124
    const int lkb = w;              // 0..7 (k rows lkb and lkb+8)
    const float* Bg = B + (size_t)lkb * N + n0 + ln;

    float acc[16][4];
#pragma unroll
    for (int i = 0; i < 16; i++)
#pragma unroll
        for (int j = 0; j < 4; j++) acc[i][j] = 0.f;

    float4 pa0 = *(const float4*)(Ag);
    float4 pa1 = *(const float4*)(Ag + 4);
    float4 pb0 = *(const float4*)(Bg);
    float4 pb1 = *(const float4*)(Bg + (size_t)8 * N);
    {
        As[0][lk + 0][lm] = totf32(pa0.x); As[0][lk + 1][lm] = totf32(pa0.y);
        As[0][lk + 2][lm] = totf32(pa0.z); As[0][lk + 3][lm] = totf32(pa0.w);
        As[0][lk + 4][lm] = totf32(pa1.x); As[0][lk + 5][lm] = totf32(pa1.y);
        As[0][lk + 6][lm] = totf32(pa1.z); As[0][lk + 7][lm] = totf32(pa1.w);
        float4 c0 = make_float4(totf32(pb0.x), totf32(pb0.y), totf32(pb0.z), totf32(pb0.w));
        float4 c1 = make_float4(totf32(pb1.x), totf32(pb1.y), totf32(pb1.z), totf32(pb1.w));
        *(float4*)&Bs[0][lkb][ln]     = c0;
        *(float4*)&Bs[0][lkb + 8][ln] = c1;
    }
    __syncthreads();

    const int KTiles = K / KTILE;
    for (int kt = 0; kt < KTiles; kt++) {
        const int cur = kt & 1;
        const bool has = (kt + 1 < KTiles);
        if (has) {
            pa0 = *(const float4*)(Ag + (kt + 1) * KTILE);
            pa1 = *(const float4*)(Ag + (kt + 1) * KTILE + 4);
            pb0 = *(const float4*)(Bg + (size_t)((kt + 1) * KTILE) * N);
            pb1 = *(const float4*)(Bg + (size_t)((kt + 1) * KTILE + 8) * N);
        }
#pragma unroll
        for (int kk = 0; kk < 2; kk++) {
            const int kb = kk * 8;
            u32 af[4][4], bf[4][2];
#pragma unroll
            for (int mi = 0; mi < 4; mi++) {
                af[mi][0] = __float_as_uint(As[cur][kb + tg    ][wm + mi * 16 + gq]);
                af[mi][1] = __float_as_uint(As[cur][kb + tg    ][wm + mi * 16 + gq + 8]);
                af[mi][2] = __float_as_uint(As[cur][kb + tg + 4][wm + mi * 16 + gq]);
                af[mi][3] = __float_as_uint(As[cur][kb + tg + 4][wm + mi * 16 + gq + 8]);
            }
#pragma unroll
            for (int ni = 0; ni < 4; ni++) {
                bf[ni][0] = __float_as_uint(Bs[cur][kb + tg    ][wn + ni * 8 + gq]);
                bf[ni][1] = __float_as_uint(Bs[cur][kb + tg + 4][wn + ni * 8 + gq]);
            }
#pragma unroll
            for (int mi = 0; mi < 4; mi++)
#pragma unroll
                for (int ni = 0; ni < 4; ni++)
                    mma_tf32(acc[mi * 4 + ni], af[mi], bf[ni]);
        }
        if (has) {
            const int nb = cur ^ 1;
            As[nb][lk + 0][lm] = totf32(pa0.x); As[nb][lk + 1][lm] = totf32(pa0.y);
            As[nb][lk + 2][lm] = totf32(pa0.z); As[nb][lk + 3][lm] = totf32(pa0.w);
            As[nb][lk + 4][lm] = totf32(pa1.x); As[nb][lk + 5][lm] = totf32(pa1.y);
            As[nb][lk + 6][lm] = totf32(pa1.z); As[nb][lk + 7][lm] = totf32(pa1.w);
            float4 c0 = make_float4(totf32(pb0.x), totf32(pb0.y), totf32(pb0.z), totf32(pb0.w));
            float4 c1 = make_float4(totf32(pb1.x), totf32(pb1.y), totf32(pb1.z), totf32(pb1.w));
            *(float4*)&Bs[nb][lkb][ln]     = c0;
            *(float4*)&Bs[nb][lkb + 8][ln] = c1;
            __syncthreads();
        }
    }

#pragma unroll
    for (int ni = 0; ni < 4; ni++) {
        const int ncol = n0 + wn + ni * 8 + tg * 2;
#pragma unroll
        for (int mi = 0; mi < 4; mi++) {
            const float* c = acc[mi * 4 + ni];
            const int mr0 = m0 + wm + mi * 16 + gq;
            float2 e0 = *(const float2*)&E[(size_t)mr0 * N + ncol];
            float2 e1 = *(const float2*)&E[(size_t)(mr0 + 8) * N + ncol];
            *(float2*)&C[(size_t)mr0 * N + ncol] =
                make_float2(c[0] + e0.x, c[1] + e0.y);
            *(float2*)&C[(size_t)(mr0 + 8) * N + ncol] =
                make_float2(c[2] + e1.x, c[3] + e1.y);
        }
    }
}

// ---------------- persistent LSTM v3 (fp32, f32x2) ----------------
// 128 blocks = 4 bg x 32 us. 128 threads: thread = (unit-pair, batch-pair).
#define WS_FLOATS (HDIM * 64)
#define HS_FLOATS (HDIM * 32)
__global__ __launch_bounds__(128, 1) void lstm_persistent3(const float* __restrict__ W_hh)
{
    extern __shared__ float sm[];
    float* ws = sm;                 // [k][64] : r = iu*4 + gate
    float* hs = sm + WS_FLOATS;     // [k][32 local b]

    const int tid = threadIdx.x;
    const int bg = blockIdx.x >> 5;
    const int us = blockIdx.x & 31;
    const int iu2 = tid >> 4;             // 0..7 unit-pair
    const int bp  = tid & 15;             // 0..15 batch-pair
    const int bl  = bp * 2;
    const int b0  = bg * 32 + bl;
    const int ugl = us * 16 + iu2 * 2;    // global unit base (2 units)

    // one-time: stage W_hh slice into smem
    {
        const int r = tid >> 1;           // 0..63
        const int iu_r = r >> 2, g_r = r & 3;
        const size_t grow = ((size_t)(g_r * HDIM + us * 16 + iu_r)) * HDIM;
        for (int k = (tid & 1) * 4; k < HDIM; k += 8) {
            float4 wv = *(const float4*)(W_hh + grow + k);
            ws[(k + 0) * 64 + r] = wv.x;
            ws[(k + 1) * 64 + r] = wv.y;
            ws[(k + 2) * 64 + r] = wv.z;
            ws[(k + 3) * 64 + r] = wv.w;
        }
    }

    // one-time: zero our slice of h0
    for (int idx = tid; idx < 16 * 32; idx += 128)
        g_h2[bg * (HDIM * 32) + (us * 16 + (idx >> 5)) * 32 + (idx & 31)] = 0.f;

    float cc[2][2] = {{0.f, 0.f}, {0.f, 0.f}};

    __syncthreads();
    // initial full barrier
    if (tid == 0) {
        __threadfence();
        volatile unsigned* genp = &g_barg[bg];
        unsigned g = *genp;
        if (atomicAdd(&g_barc[bg], 1) == 31) {
            g_barc[bg] = 0;
            __threadfence();
            atomicExch((unsigned*)&g_barg[bg], g + 1);
        } else {
            while (*genp == g) { }
        }
        __threadfence();
    }
    __syncthreads();

    const float* wp = ws + iu2 * 8;
    const float* hp = hs + bl;

    for (int t = 0; t < SDEC; t++) {
        const int cur = t & 1, nxt = cur ^ 1;

        // prefetch x-part of gates: layout [t][b][col]; float2 over unit pair
        float2 xg[4][2];   // [gate][bb]
        {
            const size_t tb = (size_t)t * B_;
#pragma unroll
            for (int g = 0; g < 4; g++)
#pragma unroll
                for (int bb = 0; bb < 2; bb++)
                    xg[g][bb] = *(const float2*)&g_xWt[(tb + b0 + bb) * G4H + g * HDIM + ugl];
        }

        // bulk-load this bg's h slice [512][32] into smem (L2-only)
        const float* hsrc = g_h2 + cur * (4 * HDIM * 32) + bg * (HDIM * 32);
        for (int i = tid * 4; i < HS_FLOATS; i += 512) {
            float4 v = __ldcg((const float4*)(hsrc + i));
            *(float4*)&hs[i] = v;
        }
        __syncthreads();

        // pure-smem GEMM: 2 units x 4 gates x 2 batch, gate-pairs in f32x2 lanes
        ull aif0a = 0, ago0a = 0, aif1a = 0, ago1a = 0;
        ull aif0b = 0, ago0b = 0, aif1b = 0, ago1b = 0;
#pragma unroll 8
        for (int k = 0; k < HDIM; k++) {
            ulonglong2 wa = *(const ulonglong2*)(wp + k * 64);       // unit a: (i,f),(g,o)
            ulonglong2 wb = *(const ulonglong2*)(wp + k * 64 + 4);   // unit b
            float2 hv = *(const float2*)(hp + k * 32);
            ull ha = dup2(hv.x);
            ull hb = dup2(hv.y);
            aif0a = ffma2(wa.x, ha, aif0a);
            ago0a = ffma2(wa.y, ha, ago0a);
            aif1a = ffma2(wb.x, ha, aif1a);
            ago1a = ffma2(wb.y, ha, ago1a);
            aif0b = ffma2(wa.x, hb, aif0b);
            ago0b = ffma2(wa.y, hb, ago0b);
            aif1b = ffma2(wb.x, hb, aif1b);
            ago1b = ffma2(wb.y, hb, ago1b);
        }

        // gates = h-part + x-part; cell + hidden update in registers
        float h[2][2];
        {
            float iv, fv, gv, ov, c;
            iv = lo32(aif0a) + xg[0][0].x; fv = hi32(aif0a) + xg[1][0].x;
            gv = lo32(ago0a) + xg[2][0].x; ov = hi32(ago0a) + xg[3][0].x;
            c = sigmoidf_(fv) * cc[0][0] + sigmoidf_(iv) * tanhf(gv);
            cc[0][0] = c; h[0][0] = sigmoidf_(ov) * tanhf(c);

            iv = lo32(aif1a) + xg[0][0].y; fv = hi32(aif1a) + xg[1][0].y;
            gv = lo32(ago1a) + xg[2][0].y; ov = hi32(ago1a) + xg[3][0].y;
            c = sigmoidf_(fv) * cc[1][0] + sigmoidf_(iv) * tanhf(gv);
            cc[1][0] = c; h[1][0] = sigmoidf_(ov) * tanhf(c);

            iv = lo32(aif0b) + xg[0][1].x; fv = hi32(aif0b) + xg[1][1].x;
            gv = lo32(ago0b) + xg[2][1].x; ov = hi32(ago0b) + xg[3][1].x;
            c = sigmoidf_(fv) * cc[0][1] + sigmoidf_(iv) * tanhf(gv);
            cc[0][1] = c; h[0][1] = sigmoidf_(ov) * tanhf(c);

            iv = lo32(aif1b) + xg[0][1].y; fv = hi32(aif1b) + xg[1][1].y;
            gv = lo32(ago1b) + xg[2][1].y; ov = hi32(ago1b) + xg[3][1].y;
            c = sigmoidf_(fv) * cc[1][1] + sigmoidf_(iv) * tanhf(gv);
            cc[1][1] = c; h[1][1] = sigmoidf_(ov) * tanhf(c);
        }

        // publish h to ping-pong, then arrive; overlap g_H stores with peers
        float* hdst = g_h2 + nxt * (4 * HDIM * 32) + bg * (HDIM * 32);
        *(float2*)&hdst[(ugl + 0) * 32 + bl] = make_float2(h[0][0], h[0][1]);
        *(float2*)&hdst[(ugl + 1) * 32 + bl] = make_float2(h[1][0], h[1][1]);

        __syncthreads();   // hs reads done + h2 writes done
        unsigned mygen = 0;
        if (tid == 0) {
            __threadfence();
            mygen = *(volatile unsigned*)&g_barg[bg];
            if (atomicAdd(&g_barc[bg], 1) == 31) {
                g_barc[bg] = 0;
                __threadfence();
                atomicExch((unsigned*)&g_barg[bg], mygen + 1);
            }
        }

        // history stores (not barrier-protected; consumed after kernel ends)
        *(float2*)&g_H[((size_t)b0 * SDEC + t) * HDIM + ugl]       = make_float2(h[0][0], h[1][0]);
        *(float2*)&g_H[((size_t)(b0 + 1) * SDEC + t) * HDIM + ugl] = make_float2(h[0][1], h[1][1]);

        if (tid == 0) {
            volatile unsigned* genp = &g_barg[bg];
            while (*genp == mygen) { }
            __threadfence();
        }
        __syncthreads();
    }
}

// ---------------- softmax over last dim (256) ----------------
__global__ __launch_bounds__(256) void softmax256(float* __restrict__ S) {
    __shared__ float red[256];
    const int t = threadIdx.x;
    float* p = S + (size_t)blockIdx.x * SENC;
    float v = p[t];
    red[t] = v; __syncthreads();
    for (int s = 128; s > 0; s >>= 1) { if (t < s) red[t] = fmaxf(red[t], red[t + s]); __syncthreads(); }
    float mx = red[0]; __syncthreads();
    float e = __expf(v - mx);
    red[t] = e; __syncthreads();
    for (int s = 128; s > 0; s >>= 1) { if (t < s) red[t] += red[t + s]; __syncthreads(); }
    p[t] = e * (1.0f / red[0]);
}

// ---------------- host ----------------
extern "C" void kernel_launch(void* const* d_in, const int* in_sizes, int n_in,
                              void* d_out, int out_size) {
    const float* x    = (const float*)d_in[0];
    const float* enc  = (const float*)d_in[1];
    const float* W_ih = (const float*)d_in[2];
    const float* W_hh = (const float*)d_in[3];
    const float* b_ih = (const float*)d_in[4];
    const float* b_hh = (const float*)d_in[5];
    const float* Wq   = (const float*)d_in[6];
    const float* bq   = (const float*)d_in[7];
    const float* Wk   = (const float*)d_in[8];
    const float* bk   = (const float*)d_in[9];
    const float* Wv   = (const float*)d_in[10];
    const float* bv   = (const float*)d_in[11];
    const float* Wfc  = (const float*)d_in[12];
    const float* bfc  = (const float*)d_in[13];
    float* out = (float*)d_out;

    float *p_xWt, *p_K, *p_V, *p_H, *p_Q, *p_HC, *p_S, *p_bsum;
    cudaGetSymbolAddress((void**)&p_xWt, g_xWt);
    cudaGetSymbolAddress((void**)&p_K,   g_K);
    cudaGetSymbolAddress((void**)&p_V,   g_V);
    cudaGetSymbolAddress((void**)&p_H,   g_H);
    cudaGetSymbolAddress((void**)&p_Q,   g_Q);
    cudaGetSymbolAddress((void**)&p_HC,  g_HC);
    cudaGetSymbolAddress((void**)&p_S,   g_S);
    cudaGetSymbolAddress((void**)&p_bsum,g_bsum);

    const float scale = 1.0f / sqrtf((float)HDIM);

    cudaFuncSetAttribute(lstm_persistent3,
                         cudaFuncAttributeMaxDynamicSharedMemorySize,
                         (WS_FLOATS + HS_FLOATS) * sizeof(float));

    bias_sum_kernel<<<G4H / 256, 256>>>(b_ih, b_hh);

    // xW = x @ W_ih^T + (b_ih+b_hh), written directly transposed to [t][b][col]
    gemm_nt_tf32<<<dim3(G4H / 128, MROWS / 128, 1), 256>>>(
        x, W_ih, p_bsum, p_xWt, MROWS, G4H, IDIM, 1.0f, 0, 0, 0, 1);
    // K = enc @ Wk^T + bk
    gemm_nt_tf32<<<dim3(HDIM / 128, MROWS / 128, 1), 256>>>(
        enc, Wk, bk, p_K, MROWS, HDIM, HDIM, 1.0f, 0, 0, 0, 0);
    // V = K @ Wv^T + bv
    gemm_nt_tf32<<<dim3(HDIM / 128, MROWS / 128, 1), 256>>>(
        p_K, Wv, bv, p_V, MROWS, HDIM, HDIM, 1.0f, 0, 0, 0, 0);

    // entire sequential LSTM in one persistent launch (fp32)
    lstm_persistent3<<<128, 128, (WS_FLOATS + HS_FLOATS) * sizeof(float)>>>(W_hh);

    // Q = H @ Wq^T + bq
    gemm_nt_tf32<<<dim3(HDIM / 128, MROWS / 128, 1), 256>>>(
        p_H, Wq, bq, p_Q, MROWS, HDIM, HDIM, 1.0f, 0, 0, 0, 0);

    // scores: per-batch S[t,s] = scale * Q[t,:]·K[s,:]
    gemm_nt_tf32<<<dim3(SENC / 128, SDEC / 128, B_), 256>>>(
        p_Q, p_K, nullptr, p_S, SDEC, SENC, HDIM, scale,
        (size_t)SDEC * HDIM, (size_t)SENC * HDIM, (size_t)SDEC * SENC, 0);

    softmax256<<<B_ * SDEC, 256>>>(p_S);

    // context + h: HC[t,h] = sum_s S[t,s] * V[s,h] + H[t,h]
    gemm_nn_addE_tf32<<<dim3(HDIM / 128, SDEC / 128, B_), 256>>>(
        p_S, p_V, p_H, p_HC, SDEC, HDIM, SENC,
        (size_t)SDEC * SENC, (size_t)SENC * HDIM,
        (size_t)SDEC * HDIM, (size_t)SDEC * HDIM);

    // out = HC @ Wfc^T + bfc
    gemm_nt_tf32<<<dim3(ODIM / 128, MROWS / 128, 1), 256>>>(
        p_HC, Wfc, bfc, out, MROWS, ODIM, HDIM, 1.0f, 0, 0, 0, 0);
}

// round 7
// speedup vs baseline: 2.7205x; 1.2834x over previous
#include <cuda_runtime.h>
#include <math.h>

#define B_    128
#define SDEC  256
#define SENC  256
#define IDIM  256
#define HDIM  512
#define ODIM  256
#define G4H   2048
#define MROWS 32768   // B_*SDEC == B_*SENC

typedef unsigned long long ull;
typedef unsigned int u32;

// ---------------- scratch (device globals; no allocs allowed) ----------------
__device__ float g_xWt[(size_t)MROWS * G4H];  // x@W_ih^T + biases, layout [t][b][col]
__device__ float g_K [(size_t)MROWS * HDIM];  // enc@Wk^T + bk
__device__ float g_V [(size_t)MROWS * HDIM];  // K@Wv^T + bv
__device__ float g_H [(size_t)MROWS * HDIM];  // all h_t  [b*256+t][u]
__device__ float g_Q [(size_t)MROWS * HDIM];  // H@Wq^T + bq
__device__ float g_HC[(size_t)MROWS * HDIM];  // h + context
__device__ float g_S [(size_t)B_ * SDEC * SENC]; // attention probs
__device__ float g_hT[2 * HDIM * B_];         // h ping-pong [pp][u][b]
__device__ float g_bsum[G4H];
__device__ unsigned g_barc;
__device__ unsigned g_barg;

__device__ __forceinline__ float sigmoidf_(float x) { return 1.0f / (1.0f + __expf(-x)); }

__device__ __forceinline__ float totf32(float x) {
    u32 r;
    asm("cvt.rna.tf32.f32 %0, %1;" : "=r"(r) : "f"(x));
    return __uint_as_float(r);
}
__device__ __forceinline__ void mma_tf32(float* c, const u32* a, const u32* b) {
    asm("mma.sync.aligned.m16n8k8.row.col.f32.tf32.tf32.f32 "
        "{%0,%1,%2,%3},{%4,%5,%6,%7},{%8,%9},{%0,%1,%2,%3};"
        : "+f"(c[0]), "+f"(c[1]), "+f"(c[2]), "+f"(c[3])
        : "r"(a[0]), "r"(a[1]), "r"(a[2]), "r"(a[3]), "r"(b[0]), "r"(b[1]));
}

// ---------------- bias sum ----------------
__global__ void bias_sum_kernel(const float* __restrict__ b_ih, const float* __restrict__ b_hh) {
    int i = blockIdx.x * 256 + threadIdx.x;
    if (i < G4H) g_bsum[i] = b_ih[i] + b_hh[i];
}

// ================= TF32 NT GEMM =================
// C[m,n] = alpha * sum_k A[m,k]*B[n,k] + bias[n].  A [M,K] rm, B [N,K] rm.
// xwmode: write C at [(t*128+b)*N + n] with m = b*256+t (fused transpose).
#define KTILE 16
__global__ __launch_bounds__(256) void gemm_nt_tf32(
    const float* __restrict__ A, const float* __restrict__ B,
    const float* __restrict__ bias, float* __restrict__ C,
    int M, int N, int K, float alpha,
    size_t sA, size_t sB, size_t sC, int xwmode)
{
    __shared__ float As[2][KTILE][136];
    __shared__ float Bs[2][KTILE][136];

    const int z = blockIdx.z;
    A += (size_t)z * sA; B += (size_t)z * sB; C += (size_t)z * sC;

    const int tid = threadIdx.x;
    const int m0 = blockIdx.y * 128, n0 = blockIdx.x * 128;
    const int w = tid >> 5, lane = tid & 31;
    const int wm = (w >> 2) * 64, wn = (w & 3) * 32;
    const int gq = lane >> 2, tg = lane & 3;

    const int lm = tid & 127;
    const int lk = (tid >> 7) * 8;
    const float* Ag = A + (size_t)(m0 + lm) * K + lk;
    const float* Bg = B + (size_t)(n0 + lm) * K + lk;

    float acc[16][4];
#pragma unroll
    for (int i = 0; i < 16; i++)
#pragma unroll
        for (int j = 0; j < 4; j++) acc[i][j] = 0.f;

    float4 pa0 = *(const float4*)(Ag);
    float4 pa1 = *(const float4*)(Ag + 4);
    float4 pb0 = *(const float4*)(Bg);
    float4 pb1 = *(const float4*)(Bg + 4);
    {
        As[0][lk + 0][lm] = totf32(pa0.x); As[0][lk + 1][lm] = totf32(pa0.y);
        As[0][lk + 2][lm] = totf32(pa0.z); As[0][lk + 3][lm] = totf32(pa0.w);
        As[0][lk + 4][lm] = totf32(pa1.x); As[0][lk + 5][lm] = totf32(pa1.y);
        As[0][lk + 6][lm] = totf32(pa1.z); As[0][lk + 7][lm] = totf32(pa1.w);
        Bs[0][lk + 0][lm] = totf32(pb0.x); Bs[0][lk + 1][lm] = totf32(pb0.y);
        Bs[0][lk + 2][lm] = totf32(pb0.z); Bs[0][lk + 3][lm] = totf32(pb0.w);
        Bs[0][lk + 4][lm] = totf32(pb1.x); Bs[0][lk + 5][lm] = totf32(pb1.y);
        Bs[0][lk + 6][lm] = totf32(pb1.z); Bs[0][lk + 7][lm] = totf32(pb1.w);
    }
    __syncthreads();

    const int KTiles = K / KTILE;
    for (int kt = 0; kt < KTiles; kt++) {
        const int cur = kt & 1;
        const bool has = (kt + 1 < KTiles);
        if (has) {
            pa0 = *(const float4*)(Ag + (kt + 1) * KTILE);
            pa1 = *(const float4*)(Ag + (kt + 1) * KTILE + 4);
            pb0 = *(const float4*)(Bg + (kt + 1) * KTILE);
            pb1 = *(const float4*)(Bg + (kt + 1) * KTILE + 4);
        }
#pragma unroll
        for (int kk = 0; kk < 2; kk++) {
            const int kb = kk * 8;
            u32 af[4][4], bf[4][2];
#pragma unroll
            for (int mi = 0; mi < 4; mi++) {
                af[mi][0] = __float_as_uint(As[cur][kb + tg    ][wm + mi * 16 + gq]);
                af[mi][1] = __float_as_uint(As[cur][kb + tg    ][wm + mi * 16 + gq + 8]);
                af[mi][2] = __float_as_uint(As[cur][kb + tg + 4][wm + mi * 16 + gq]);
                af[mi][3] = __float_as_uint(As[cur][kb + tg + 4][wm + mi * 16 + gq + 8]);
            }
#pragma unroll
            for (int ni = 0; ni < 4; ni++) {
                bf[ni][0] = __float_as_uint(Bs[cur][kb + tg    ][wn + ni * 8 + gq]);
                bf[ni][1] = __float_as_uint(Bs[cur][kb + tg + 4][wn + ni * 8 + gq]);
            }
#pragma unroll
            for (int mi = 0; mi < 4; mi++)
#pragma unroll
                for (int ni = 0; ni < 4; ni++)
                    mma_tf32(acc[mi * 4 + ni], af[mi], bf[ni]);
        }
        if (has) {
            const int nb = cur ^ 1;
            As[nb][lk + 0][lm] = totf32(pa0.x); As[nb][lk + 1][lm] = totf32(pa0.y);
            As[nb][lk + 2][lm] = totf32(pa0.z); As[nb][lk + 3][lm] = totf32(pa0.w);
            As[nb][lk + 4][lm] = totf32(pa1.x); As[nb][lk + 5][lm] = totf32(pa1.y);
            As[nb][lk + 6][lm] = totf32(pa1.z); As[nb][lk + 7][lm] = totf32(pa1.w);
            Bs[nb][lk + 0][lm] = totf32(pb0.x); Bs[nb][lk + 1][lm] = totf32(pb0.y);
            Bs[nb][lk + 2][lm] = totf32(pb0.z); Bs[nb][lk + 3][lm] = totf32(pb0.w);
            Bs[nb][lk + 4][lm] = totf32(pb1.x); Bs[nb][lk + 5][lm] = totf32(pb1.y);
            Bs[nb][lk + 6][lm] = totf32(pb1.z); Bs[nb][lk + 7][lm] = totf32(pb1.w);
            __syncthreads();
        }
    }

#pragma unroll
    for (int ni = 0; ni < 4; ni++) {
        const int ncol = n0 + wn + ni * 8 + tg * 2;
        float2 bv = make_float2(0.f, 0.f);
        if (bias) bv = *(const float2*)&bias[ncol];
#pragma unroll
        for (int mi = 0; mi < 4; mi++) {
            const float* c = acc[mi * 4 + ni];
            const int mr0 = m0 + wm + mi * 16 + gq;
            float2 lo = make_float2(alpha * c[0] + bv.x, alpha * c[1] + bv.y);
            float2 hi = make_float2(alpha * c[2] + bv.x, alpha * c[3] + bv.y);
            if (xwmode) {
                const int bb = mr0 >> 8, t0 = mr0 & 255;
                *(float2*)&C[((size_t)t0 * B_ + bb) * N + ncol]       = lo;
                *(float2*)&C[((size_t)(t0 + 8) * B_ + bb) * N + ncol] = hi;
            } else {
                *(float2*)&C[(size_t)mr0 * N + ncol]       = lo;
                *(float2*)&C[(size_t)(mr0 + 8) * N + ncol] = hi;
            }
        }
    }
}

// ================= TF32 NN GEMM + E add =================
__global__ __launch_bounds__(256) void gemm_nn_addE_tf32(
    const float* __restrict__ A, const float* __restrict__ B,
    const float* __restrict__ E, float* __restrict__ C,
    int M, int N, int K,
    size_t sA, size_t sB, size_t sE, size_t sC)
{
    __shared__ float As[2][KTILE][136];
    __shared__ float Bs[2][KTILE][136];

    const int z = blockIdx.z;
    A += (size_t)z * sA; B += (size_t)z * sB; E += (size_t)z * sE; C += (size_t)z * sC;

    const int tid = threadIdx.x;
    const int m0 = blockIdx.y * 128, n0 = blockIdx.x * 128;
    const int w = tid >> 5, lane = tid & 31;
    const int wm = (w >> 2) * 64, wn = (w & 3) * 32;
    const int gq = lane >> 2, tg = lane & 3;

    const int lm = tid & 127;
    const int lk = (tid >> 7) * 8;
    const float* Ag = A + (size_t)(m0 + lm) * K + lk;
    const int ln  = lane * 4;
    const int lkb = w;
    const float* Bg = B + (size_t)lkb * N + n0 + ln;

    float acc[16][4];
#pragma unroll
    for (int i = 0; i < 16; i++)
#pragma unroll
        for (int j = 0; j < 4; j++) acc[i][j] = 0.f;

    float4 pa0 = *(const float4*)(Ag);
    float4 pa1 = *(const float4*)(Ag + 4);
    float4 pb0 = *(const float4*)(Bg);
    float4 pb1 = *(const float4*)(Bg + (size_t)8 * N);
    {
        As[0][lk + 0][lm] = totf32(pa0.x); As[0][lk + 1][lm] = totf32(pa0.y);
        As[0][lk + 2][lm] = totf32(pa0.z); As[0][lk + 3][lm] = totf32(pa0.w);
        As[0][lk + 4][lm] = totf32(pa1.x); As[0][lk + 5][lm] = totf32(pa1.y);
        As[0][lk + 6][lm] = totf32(pa1.z); As[0][lk + 7][lm] = totf32(pa1.w);
        float4 c0 = make_float4(totf32(pb0.x), totf32(pb0.y), totf32(pb0.z), totf32(pb0.w));
        float4 c1 = make_float4(totf32(pb1.x), totf32(pb1.y), totf32(pb1.z), totf32(pb1.w));
        *(float4*)&Bs[0][lkb][ln]     = c0;
        *(float4*)&Bs[0][lkb + 8][ln] = c1;
    }
    __syncthreads();

    const int KTiles = K / KTILE;
    for (int kt = 0; kt < KTiles; kt++) {
        const int cur = kt & 1;
        const bool has = (kt + 1 < KTiles);
        if (has) {
            pa0 = *(const float4*)(Ag + (kt + 1) * KTILE);
            pa1 = *(const float4*)(Ag + (kt + 1) * KTILE + 4);
            pb0 = *(const float4*)(Bg + (size_t)((kt + 1) * KTILE) * N);
            pb1 = *(const float4*)(Bg + (size_t)((kt + 1) * KTILE + 8) * N);
        }
#pragma unroll
        for (int kk = 0; kk < 2; kk++) {
            const int kb = kk * 8;
            u32 af[4][4], bf[4][2];
#pragma unroll
            for (int mi = 0; mi < 4; mi++) {
                af[mi][0] = __float_as_uint(As[cur][kb + tg    ][wm + mi * 16 + gq]);
                af[mi][1] = __float_as_uint(As[cur][kb + tg    ][wm + mi * 16 + gq + 8]);
                af[mi][2] = __float_as_uint(As[cur][kb + tg + 4][wm + mi * 16 + gq]);
                af[mi][3] = __float_as_uint(As[cur][kb + tg + 4][wm + mi * 16 + gq + 8]);
            }
#pragma unroll
            for (int ni = 0; ni < 4; ni++) {
                bf[ni][0] = __float_as_uint(Bs[cur][kb + tg    ][wn + ni * 8 + gq]);
                bf[ni][1] = __float_as_uint(Bs[cur][kb + tg + 4][wn + ni * 8 + gq]);
            }
#pragma unroll
            for (int mi = 0; mi < 4; mi++)
#pragma unroll
                for (int ni = 0; ni < 4; ni++)
                    mma_tf32(acc[mi * 4 + ni], af[mi], bf[ni]);
        }
        if (has) {
            const int nb = cur ^ 1;
            As[nb][lk + 0][lm] = totf32(pa0.x); As[nb][lk + 1][lm] = totf32(pa0.y);
            As[nb][lk + 2][lm] = totf32(pa0.z); As[nb][lk + 3][lm] = totf32(pa0.w);
            As[nb][lk + 4][lm] = totf32(pa1.x); As[nb][lk + 5][lm] = totf32(pa1.y);
            As[nb][lk + 6][lm] = totf32(pa1.z); As[nb][lk + 7][lm] = totf32(pa1.w);
            float4 c0 = make_float4(totf32(pb0.x), totf32(pb0.y), totf32(pb0.z), totf32(pb0.w));
            float4 c1 = make_float4(totf32(pb1.x), totf32(pb1.y), totf32(pb1.z), totf32(pb1.w));
            *(float4*)&Bs[nb][lkb][ln]     = c0;
            *(float4*)&Bs[nb][lkb + 8][ln] = c1;
            __syncthreads();
        }
    }

#pragma unroll
    for (int ni = 0; ni < 4; ni++) {
        const int ncol = n0 + wn + ni * 8 + tg * 2;
#pragma unroll
        for (int mi = 0; mi < 4; mi++) {
            const float* c = acc[mi * 4 + ni];
            const int mr0 = m0 + wm + mi * 16 + gq;
            float2 e0 = *(const float2*)&E[(size_t)mr0 * N + ncol];
            float2 e1 = *(const float2*)&E[(size_t)(mr0 + 8) * N + ncol];
            *(float2*)&C[(size_t)mr0 * N + ncol] =
                make_float2(c[0] + e0.x, c[1] + e0.y);
            *(float2*)&C[(size_t)(mr0 + 8) * N + ncol] =
                make_float2(c[2] + e1.x, c[3] + e1.y);
        }
    }
}

// ================= persistent tensor-core LSTM =================
// 128 blocks = 2 batch-halves (mh) x 64 unit-slices (nb, 8 units = 32 gate-cols).
// W slice in smem as TF32 (staged once, gate-interleaved). Per step: stage the
// 64x512 h-half into smem, 128 m16n8k8 TF32 mma/warp, in-register cell update
// (c-state lives in regs all 256 steps), shfl gate-exchange, global barrier.
#define AH_STRIDE 72
#define WS_STRIDE 516
#define SM_FLOATS (HDIM * AH_STRIDE + 32 * WS_STRIDE)
__global__ __launch_bounds__(256, 1) void lstm_tensor(const float* __restrict__ W_hh)
{
    extern __shared__ float sm[];
    float* Ah = sm;                          // [512][72]   h tile (tf32)
    float* Ws = sm + HDIM * AH_STRIDE;       // [32][516]   W slice (tf32)

    const int tid = threadIdx.x;
    const int lane = tid & 31, w = tid >> 5;
    const int gq = lane >> 2, tg = lane & 3;
    const int mt = w & 3, nh = w >> 2;       // m-tile (16 rows), n-half (16 cols)
    const int mh = blockIdx.x & 1, nb = blockIdx.x >> 1;
    const int u0 = nb * 8;
    const int mrow0 = mh * 64 + mt * 16;     // global batch-row base for this warp

    // ---- one-time: stage W slice as TF32, gate-interleaved: col j = (unit u0+(j>>2), gate j&3)
    for (int i = tid; i < 32 * 128; i += 256) {
        const int j = i >> 7, k = (i & 127) * 4;
        const int unit = u0 + (j >> 2), gate = j & 3;
        float4 wv = *(const float4*)(W_hh + (size_t)(gate * HDIM + unit) * HDIM + k);
        Ws[j * WS_STRIDE + k + 0] = totf32(wv.x);
        Ws[j * WS_STRIDE + k + 1] = totf32(wv.y);
        Ws[j * WS_STRIDE + k + 2] = totf32(wv.z);
        Ws[j * WS_STRIDE + k + 3] = totf32(wv.w);
    }

    // ---- one-time: zero h0 ping buffer (mh==0 blocks cover all units)
    if (mh == 0) {
        for (int i = tid; i < 8 * B_; i += 256)
            g_hT[(u0 + (i >> 7)) * B_ + (i & 127)] = 0.f;
    }

    float cst[2] = {0.f, 0.f};   // c-state: one row x one unit per n8

    __threadfence();
    __syncthreads();
    if (tid == 0) {
        volatile unsigned* genp = &g_barg;
        unsigned g = *genp;
        if (atomicAdd(&g_barc, 1) == 127) {
            g_barc = 0; __threadfence();
            atomicExch((unsigned*)&g_barg, g + 1);
        } else { while (*genp == g) { } }
        __threadfence();
    }
    __syncthreads();

    // per-thread unit/gate mapping for the epilogue (independent of ni offset)
    const int gA = (tg & 1) ? 2 : 0;         // own gate pair: (i,f) or (g,o)

    for (int t = 0; t < SDEC; t++) {
        const int cur = t & 1, nxt = cur ^ 1;

        // ---- prefetch x-part of gates (8 scattered LDG; consumed at epilogue)
        float xg[2][4];
#pragma unroll
        for (int ni = 0; ni < 2; ni++) {
            const int u = u0 + nh * 4 + ni * 2 + (tg >> 1);
            const int cA = gA * HDIM + u, cB = cA + HDIM;
            const size_t r0 = ((size_t)t * B_ + mrow0 + gq) * G4H;
            const size_t r1 = r0 + (size_t)8 * G4H;
            xg[ni][0] = __ldg(&g_xWt[r0 + cA]);
            xg[ni][1] = __ldg(&g_xWt[r0 + cB]);
            xg[ni][2] = __ldg(&g_xWt[r1 + cA]);
            xg[ni][3] = __ldg(&g_xWt[r1 + cB]);
        }

        // ---- stage h half [512 u][64 b] into smem as TF32 (L2-only reads)
        {
            const float* src = g_hT + cur * (HDIM * B_) + mh * 64;
            for (int i = tid; i < HDIM * 16; i += 256) {
                const int row = i >> 4, seg = (i & 15) * 4;
                float4 v = __ldcg((const float4*)(src + (size_t)row * B_ + seg));
                float* d = Ah + row * AH_STRIDE + seg;
                d[0] = totf32(v.x); d[1] = totf32(v.y);
                d[2] = totf32(v.z); d[3] = totf32(v.w);
            }
        }
        __syncthreads();

        // ---- mma mainloop: 64 k-steps, dual accumulator chains
        float accA[2][4] = {{0,0,0,0},{0,0,0,0}};
        float accB[2][4] = {{0,0,0,0},{0,0,0,0}};
#pragma unroll 4
        for (int kk = 0; kk < 64; kk++) {
            const int k0 = kk * 8;
            u32 af[4];
            af[0] = __float_as_uint(Ah[(k0 + tg    ) * AH_STRIDE + mt * 16 + gq]);
            af[1] = __float_as_uint(Ah[(k0 + tg    ) * AH_STRIDE + mt * 16 + gq + 8]);
            af[2] = __float_as_uint(Ah[(k0 + tg + 4) * AH_STRIDE + mt * 16 + gq]);
            af[3] = __float_as_uint(Ah[(k0 + tg + 4) * AH_STRIDE + mt * 16 + gq + 8]);
            u32 bf0[2], bf1[2];
            bf0[0] = __float_as_uint(Ws[(nh * 16 + gq    ) * WS_STRIDE + k0 + tg]);
            bf0[1] = __float_as_uint(Ws[(nh * 16 + gq    ) * WS_STRIDE + k0 + tg + 4]);
            bf1[0] = __float_as_uint(Ws[(nh * 16 + 8 + gq) * WS_STRIDE + k0 + tg]);
            bf1[1] = __float_as_uint(Ws[(nh * 16 + 8 + gq) * WS_STRIDE + k0 + tg + 4]);
            if (kk & 1) { mma_tf32(accB[0], af, bf0); mma_tf32(accB[1], af, bf1); }
            else        { mma_tf32(accA[0], af, bf0); mma_tf32(accA[1], af, bf1); }
        }

        // ---- epilogue: gates -> shuffle -> cell update -> h stores
#pragma unroll
        for (int ni = 0; ni < 2; ni++) {
            float v0 = accA[ni][0] + accB[ni][0] + xg[ni][0];
            float v1 = accA[ni][1] + accB[ni][1] + xg[ni][1];
            float v2 = accA[ni][2] + accB[ni][2] + xg[ni][2];
            float v3 = accA[ni][3] + accB[ni][3] + xg[ni][3];
            float r0 = __shfl_xor_sync(0xffffffffu, v0, 1);
            float r1 = __shfl_xor_sync(0xffffffffu, v1, 1);
            float r2 = __shfl_xor_sync(0xffffffffu, v2, 1);
            float r3 = __shfl_xor_sync(0xffffffffu, v3, 1);
            float iv, fv, gv, ov; int b;
            if (tg & 1) { iv = r2; fv = r3; gv = v2; ov = v3; b = mrow0 + gq + 8; }
            else        { iv = v0; fv = v1; gv = r0; ov = r1; b = mrow0 + gq; }
            float c = sigmoidf_(fv) * cst[ni] + sigmoidf_(iv) * tanhf(gv);
            cst[ni] = c;
            float h = sigmoidf_(ov) * tanhf(c);
            const int u = u0 + nh * 4 + ni * 2 + (tg >> 1);
            g_hT[nxt * (HDIM * B_) + u * B_ + b] = h;
            g_H[((size_t)b * SDEC + t) * HDIM + u] = h;
        }

        __threadfence();
        __syncthreads();
        if (tid == 0) {
            volatile unsigned* genp = &g_barg;
            unsigned g = *genp;
            if (atomicAdd(&g_barc, 1) == 127) {
                g_barc = 0; __threadfence();
                atomicExch((unsigned*)&g_barg, g + 1);
            } else { while (*genp == g) { } }
            __threadfence();
        }
        __syncthreads();
    }
}

// ---------------- softmax over last dim (256) ----------------
__global__ __launch_bounds__(256) void softmax256(float* __restrict__ S) {
    __shared__ float red[256];
    const int t = threadIdx.x;
    float* p = S + (size_t)blockIdx.x * SENC;
    float v = p[t];
    red[t] = v; __syncthreads();
    for (int s = 128; s > 0; s >>= 1) { if (t < s) red[t] = fmaxf(red[t], red[t + s]); __syncthreads(); }
    float mx = red[0]; __syncthreads();
    float e = __expf(v - mx);
    red[t] = e; __syncthreads();
    for (int s = 128; s > 0; s >>= 1) { if (t < s) red[t] += red[t + s]; __syncthreads(); }
    p[t] = e * (1.0f / red[0]);
}

// ---------------- host ----------------
extern "C" void kernel_launch(void* const* d_in, const int* in_sizes, int n_in,
                              void* d_out, int out_size) {
    const float* x    = (const float*)d_in[0];
    const float* enc  = (const float*)d_in[1];
    const float* W_ih = (const float*)d_in[2];
    const float* W_hh = (const float*)d_in[3];
    const float* b_ih = (const float*)d_in[4];
    const float* b_hh = (const float*)d_in[5];
    const float* Wq   = (const float*)d_in[6];
    const float* bq   = (const float*)d_in[7];
    const float* Wk   = (const float*)d_in[8];
    const float* bk   = (const float*)d_in[9];
    const float* Wv   = (const float*)d_in[10];
    const float* bv   = (const float*)d_in[11];
    const float* Wfc  = (const float*)d_in[12];
    const float* bfc  = (const float*)d_in[13];
    float* out = (float*)d_out;

    float *p_xWt, *p_K, *p_V, *p_H, *p_Q, *p_HC, *p_S, *p_bsum;
    cudaGetSymbolAddress((void**)&p_xWt, g_xWt);
    cudaGetSymbolAddress((void**)&p_K,   g_K);
    cudaGetSymbolAddress((void**)&p_V,   g_V);
    cudaGetSymbolAddress((void**)&p_H,   g_H);
    cudaGetSymbolAddress((void**)&p_Q,   g_Q);
    cudaGetSymbolAddress((void**)&p_HC,  g_HC);
    cudaGetSymbolAddress((void**)&p_S,   g_S);
    cudaGetSymbolAddress((void**)&p_bsum,g_bsum);

    const float scale = 1.0f / sqrtf((float)HDIM);

    cudaFuncSetAttribute(lstm_tensor,
                         cudaFuncAttributeMaxDynamicSharedMemorySize,
                         SM_FLOATS * sizeof(float));

    bias_sum_kernel<<<G4H / 256, 256>>>(b_ih, b_hh);

    // xW = x @ W_ih^T + (b_ih+b_hh), written transposed to [t][b][col]
    gemm_nt_tf32<<<dim3(G4H / 128, MROWS / 128, 1), 256>>>(
        x, W_ih, p_bsum, p_xWt, MROWS, G4H, IDIM, 1.0f, 0, 0, 0, 1);
    // K = enc @ Wk^T + bk
    gemm_nt_tf32<<<dim3(HDIM / 128, MROWS / 128, 1), 256>>>(
        enc, Wk, bk, p_K, MROWS, HDIM, HDIM, 1.0f, 0, 0, 0, 0);
    // V = K @ Wv^T + bv
    gemm_nt_tf32<<<dim3(HDIM / 128, MROWS / 128, 1), 256>>>(
        p_K, Wv, bv, p_V, MROWS, HDIM, HDIM, 1.0f, 0, 0, 0, 0);

    // entire sequential LSTM in one persistent tensor-core launch
    lstm_tensor<<<128, 256, SM_FLOATS * sizeof(float)>>>(W_hh);

    // Q = H @ Wq^T + bq
    gemm_nt_tf32<<<dim3(HDIM / 128, MROWS / 128, 1), 256>>>(
        p_H, Wq, bq, p_Q, MROWS, HDIM, HDIM, 1.0f, 0, 0, 0, 0);

    // scores: per-batch S[t,s] = scale * Q[t,:]·K[s,:]
    gemm_nt_tf32<<<dim3(SENC / 128, SDEC / 128, B_), 256>>>(
        p_Q, p_K, nullptr, p_S, SDEC, SENC, HDIM, scale,
        (size_t)SDEC * HDIM, (size_t)SENC * HDIM, (size_t)SDEC * SENC, 0);

    softmax256<<<B_ * SDEC, 256>>>(p_S);

    // context + h: HC[t,h] = sum_s S[t,s] * V[s,h] + H[t,h]
    gemm_nn_addE_tf32<<<dim3(HDIM / 128, SDEC / 128, B_), 256>>>(
        p_S, p_V, p_H, p_HC, SDEC, HDIM, SENC,
        (size_t)SDEC * SENC, (size_t)SENC * HDIM,
        (size_t)SDEC * HDIM, (size_t)SDEC * HDIM);

    // out = HC @ Wfc^T + bfc
    gemm_nt_tf32<<<dim3(ODIM / 128, MROWS / 128, 1), 256>>>(
        p_HC, Wfc, bfc, out, MROWS, ODIM, HDIM, 1.0f, 0, 0, 0, 0);
}

// round 8
// speedup vs baseline: 2.9879x; 1.0983x over previous
#include <cuda_runtime.h>
#include <math.h>

#define B_    128
#define SDEC  256
#define SENC  256
#define IDIM  256
#define HDIM  512
#define ODIM  256
#define G4H   2048
#define MROWS 32768   // B_*SDEC == B_*SENC

typedef unsigned long long ull;
typedef unsigned int u32;

// ---------------- scratch (device globals; no allocs allowed) ----------------
__device__ float g_xWt[(size_t)MROWS * G4H];  // x@W_ih^T + biases, layout [t][b][col]
__device__ float g_K [(size_t)MROWS * HDIM];  // enc@Wk^T + bk
__device__ float g_V [(size_t)MROWS * HDIM];  // K@Wv^T + bv
__device__ float g_H [(size_t)MROWS * HDIM];  // all h_t  [b*256+t][u]
__device__ float g_Q [(size_t)MROWS * HDIM];  // H@Wq^T + bq
__device__ float g_HC[(size_t)MROWS * HDIM];  // h + context
__device__ float g_S [(size_t)B_ * SDEC * SENC]; // attention probs
__device__ float g_hT[2 * HDIM * B_];         // h ping-pong [pp][u][b], tf32-rounded
__device__ float g_bsum[G4H];
__device__ unsigned g_barc;
__device__ unsigned g_barg;

__device__ __forceinline__ float sigmoidf_(float x) { return 1.0f / (1.0f + __expf(-x)); }

__device__ __forceinline__ float totf32(float x) {
    u32 r;
    asm("cvt.rna.tf32.f32 %0, %1;" : "=r"(r) : "f"(x));
    return __uint_as_float(r);
}
__device__ __forceinline__ void mma_tf32(float* c, const u32* a, const u32* b) {
    asm("mma.sync.aligned.m16n8k8.row.col.f32.tf32.tf32.f32 "
        "{%0,%1,%2,%3},{%4,%5,%6,%7},{%8,%9},{%0,%1,%2,%3};"
        : "+f"(c[0]), "+f"(c[1]), "+f"(c[2]), "+f"(c[3])
        : "r"(a[0]), "r"(a[1]), "r"(a[2]), "r"(a[3]), "r"(b[0]), "r"(b[1]));
}
__device__ __forceinline__ void cp16(float* dst_smem, const float* src) {
    u32 d = (u32)__cvta_generic_to_shared(dst_smem);
    asm volatile("cp.async.cg.shared.global [%0], [%1], 16;" :: "r"(d), "l"(src));
}

// ---------------- bias sum ----------------
__global__ void bias_sum_kernel(const float* __restrict__ b_ih, const float* __restrict__ b_hh) {
    int i = blockIdx.x * 256 + threadIdx.x;
    if (i < G4H) g_bsum[i] = b_ih[i] + b_hh[i];
}

// ================= TF32 NT GEMM (unchanged from R7) =================
#define KTILE 16
__global__ __launch_bounds__(256) void gemm_nt_tf32(
    const float* __restrict__ A, const float* __restrict__ B,
    const float* __restrict__ bias, float* __restrict__ C,
    int M, int N, int K, float alpha,
    size_t sA, size_t sB, size_t sC, int xwmode)
{
    __shared__ float As[2][KTILE][136];
    __shared__ float Bs[2][KTILE][136];

    const int z = blockIdx.z;
    A += (size_t)z * sA; B += (size_t)z * sB; C += (size_t)z * sC;

    const int tid = threadIdx.x;
    const int m0 = blockIdx.y * 128, n0 = blockIdx.x * 128;
    const int w = tid >> 5, lane = tid & 31;
    const int wm = (w >> 2) * 64, wn = (w & 3) * 32;
    const int gq = lane >> 2, tg = lane & 3;

    const int lm = tid & 127;
    const int lk = (tid >> 7) * 8;
    const float* Ag = A + (size_t)(m0 + lm) * K + lk;
    const float* Bg = B + (size_t)(n0 + lm) * K + lk;

    float acc[16][4];
#pragma unroll
    for (int i = 0; i < 16; i++)
#pragma unroll
        for (int j = 0; j < 4; j++) acc[i][j] = 0.f;

    float4 pa0 = *(const float4*)(Ag);
    float4 pa1 = *(const float4*)(Ag + 4);
    float4 pb0 = *(const float4*)(Bg);
    float4 pb1 = *(const float4*)(Bg + 4);
    {
        As[0][lk + 0][lm] = totf32(pa0.x); As[0][lk + 1][lm] = totf32(pa0.y);
        As[0][lk + 2][lm] = totf32(pa0.z); As[0][lk + 3][lm] = totf32(pa0.w);
        As[0][lk + 4][lm] = totf32(pa1.x); As[0][lk + 5][lm] = totf32(pa1.y);
        As[0][lk + 6][lm] = totf32(pa1.z); As[0][lk + 7][lm] = totf32(pa1.w);
        Bs[0][lk + 0][lm] = totf32(pb0.x); Bs[0][lk + 1][lm] = totf32(pb0.y);
        Bs[0][lk + 2][lm] = totf32(pb0.z); Bs[0][lk + 3][lm] = totf32(pb0.w);
        Bs[0][lk + 4][lm] = totf32(pb1.x); Bs[0][lk + 5][lm] = totf32(pb1.y);
        Bs[0][lk + 6][lm] = totf32(pb1.z); Bs[0][lk + 7][lm] = totf32(pb1.w);
    }
    __syncthreads();

    const int KTiles = K / KTILE;
    for (int kt = 0; kt < KTiles; kt++) {
        const int cur = kt & 1;
        const bool has = (kt + 1 < KTiles);
        if (has) {
            pa0 = *(const float4*)(Ag + (kt + 1) * KTILE);
            pa1 = *(const float4*)(Ag + (kt + 1) * KTILE + 4);
            pb0 = *(const float4*)(Bg + (kt + 1) * KTILE);
            pb1 = *(const float4*)(Bg + (kt + 1) * KTILE + 4);
        }
#pragma unroll
        for (int kk = 0; kk < 2; kk++) {
            const int kb = kk * 8;
            u32 af[4][4], bf[4][2];
#pragma unroll
            for (int mi = 0; mi < 4; mi++) {
                af[mi][0] = __float_as_uint(As[cur][kb + tg    ][wm + mi * 16 + gq]);
                af[mi][1] = __float_as_uint(As[cur][kb + tg    ][wm + mi * 16 + gq + 8]);
                af[mi][2] = __float_as_uint(As[cur][kb + tg + 4][wm + mi * 16 + gq]);
                af[mi][3] = __float_as_uint(As[cur][kb + tg + 4][wm + mi * 16 + gq + 8]);
            }
#pragma unroll
            for (int ni = 0; ni < 4; ni++) {
                bf[ni][0] = __float_as_uint(Bs[cur][kb + tg    ][wn + ni * 8 + gq]);
                bf[ni][1] = __float_as_uint(Bs[cur][kb + tg + 4][wn + ni * 8 + gq]);
            }
#pragma unroll
            for (int mi = 0; mi < 4; mi++)
#pragma unroll
                for (int ni = 0; ni < 4; ni++)
                    mma_tf32(acc[mi * 4 + ni], af[mi], bf[ni]);
        }
        if (has) {
            const int nb = cur ^ 1;
            As[nb][lk + 0][lm] = totf32(pa0.x); As[nb][lk + 1][lm] = totf32(pa0.y);
            As[nb][lk + 2][lm] = totf32(pa0.z); As[nb][lk + 3][lm] = totf32(pa0.w);
            As[nb][lk + 4][lm] = totf32(pa1.x); As[nb][lk + 5][lm] = totf32(pa1.y);
            As[nb][lk + 6][lm] = totf32(pa1.z); As[nb][lk + 7][lm] = totf32(pa1.w);
            Bs[nb][lk + 0][lm] = totf32(pb0.x); Bs[nb][lk + 1][lm] = totf32(pb0.y);
            Bs[nb][lk + 2][lm] = totf32(pb0.z); Bs[nb][lk + 3][lm] = totf32(pb0.w);
            Bs[nb][lk + 4][lm] = totf32(pb1.x); Bs[nb][lk + 5][lm] = totf32(pb1.y);
            Bs[nb][lk + 6][lm] = totf32(pb1.z); Bs[nb][lk + 7][lm] = totf32(pb1.w);
            __syncthreads();
        }
    }

#pragma unroll
    for (int ni = 0; ni < 4; ni++) {
        const int ncol = n0 + wn + ni * 8 + tg * 2;
        float2 bv = make_float2(0.f, 0.f);
        if (bias) bv = *(const float2*)&bias[ncol];
#pragma unroll
        for (int mi = 0; mi < 4; mi++) {
            const float* c = acc[mi * 4 + ni];
            const int mr0 = m0 + wm + mi * 16 + gq;
            float2 lo = make_float2(alpha * c[0] + bv.x, alpha * c[1] + bv.y);
            float2 hi = make_float2(alpha * c[2] + bv.x, alpha * c[3] + bv.y);
            if (xwmode) {
                const int bb = mr0 >> 8, t0 = mr0 & 255;
                *(float2*)&C[((size_t)t0 * B_ + bb) * N + ncol]       = lo;
                *(float2*)&C[((size_t)(t0 + 8) * B_ + bb) * N + ncol] = hi;
            } else {
                *(float2*)&C[(size_t)mr0 * N + ncol]       = lo;
                *(float2*)&C[(size_t)(mr0 + 8) * N + ncol] = hi;
            }
        }
    }
}

// ================= TF32 NN GEMM + E add (unchanged from R7) =================
__global__ __launch_bounds__(256) void gemm_nn_addE_tf32(
    const float* __restrict__ A, const float* __restrict__ B,
    const float* __restrict__ E, float* __restrict__ C,
    int M, int N, int K,
    size_t sA, size_t sB, size_t sE, size_t sC)
{
    __shared__ float As[2][KTILE][136];
    __shared__ float Bs[2][KTILE][136];

    const int z = blockIdx.z;
    A += (size_t)z * sA; B += (size_t)z * sB; E += (size_t)z * sE; C += (size_t)z * sC;

    const int tid = threadIdx.x;
    const int m0 = blockIdx.y * 128, n0 = blockIdx.x * 128;
    const int w = tid >> 5, lane = tid & 31;
    const int wm = (w >> 2) * 64, wn = (w & 3) * 32;
    const int gq = lane >> 2, tg = lane & 3;

    const int lm = tid & 127;
    const int lk = (tid >> 7) * 8;
    const float* Ag = A + (size_t)(m0 + lm) * K + lk;
    const int ln  = lane * 4;
    const int lkb = w;
    const float* Bg = B + (size_t)lkb * N + n0 + ln;

    float acc[16][4];
#pragma unroll
    for (int i = 0; i < 16; i++)
#pragma unroll
        for (int j = 0; j < 4; j++) acc[i][j] = 0.f;

    float4 pa0 = *(const float4*)(Ag);
    float4 pa1 = *(const float4*)(Ag + 4);
    float4 pb0 = *(const float4*)(Bg);
    float4 pb1 = *(const float4*)(Bg + (size_t)8 * N);
    {
        As[0][lk + 0][lm] = totf32(pa0.x); As[0][lk + 1][lm] = totf32(pa0.y);
        As[0][lk + 2][lm] = totf32(pa0.z); As[0][lk + 3][lm] = totf32(pa0.w);
        As[0][lk + 4][lm] = totf32(pa1.x); As[0][lk + 5][lm] = totf32(pa1.y);
        As[0][lk + 6][lm] = totf32(pa1.z); As[0][lk + 7][lm] = totf32(pa1.w);
        float4 c0 = make_float4(totf32(pb0.x), totf32(pb0.y), totf32(pb0.z), totf32(pb0.w));
        float4 c1 = make_float4(totf32(pb1.x), totf32(pb1.y), totf32(pb1.z), totf32(pb1.w));
        *(float4*)&Bs[0][lkb][ln]     = c0;
        *(float4*)&Bs[0][lkb + 8][ln] = c1;
    }
    __syncthreads();

    const int KTiles = K / KTILE;
    for (int kt = 0; kt < KTiles; kt++) {
        const int cur = kt & 1;
        const bool has = (kt + 1 < KTiles);
        if (has) {
            pa0 = *(const float4*)(Ag + (kt + 1) * KTILE);
            pa1 = *(const float4*)(Ag + (kt + 1) * KTILE + 4);
            pb0 = *(const float4*)(Bg + (size_t)((kt + 1) * KTILE) * N);
            pb1 = *(const float4*)(Bg + (size_t)((kt + 1) * KTILE + 8) * N);
        }
#pragma unroll
        for (int kk = 0; kk < 2; kk++) {
            const int kb = kk * 8;
            u32 af[4][4], bf[4][2];
#pragma unroll
            for (int mi = 0; mi < 4; mi++) {
                af[mi][0] = __float_as_uint(As[cur][kb + tg    ][wm + mi * 16 + gq]);
                af[mi][1] = __float_as_uint(As[cur][kb + tg    ][wm + mi * 16 + gq + 8]);
                af[mi][2] = __float_as_uint(As[cur][kb + tg + 4][wm + mi * 16 + gq]);
                af[mi][3] = __float_as_uint(As[cur][kb + tg + 4][wm + mi * 16 + gq + 8]);
            }
#pragma unroll
            for (int ni = 0; ni < 4; ni++) {
                bf[ni][0] = __float_as_uint(Bs[cur][kb + tg    ][wn + ni * 8 + gq]);
                bf[ni][1] = __float_as_uint(Bs[cur][kb + tg + 4][wn + ni * 8 + gq]);
            }
#pragma unroll
            for (int mi = 0; mi < 4; mi++)
#pragma unroll
                for (int ni = 0; ni < 4; ni++)
                    mma_tf32(acc[mi * 4 + ni], af[mi], bf[ni]);
        }
        if (has) {
            const int nb = cur ^ 1;
            As[nb][lk + 0][lm] = totf32(pa0.x); As[nb][lk + 1][lm] = totf32(pa0.y);
            As[nb][lk + 2][lm] = totf32(pa0.z); As[nb][lk + 3][lm] = totf32(pa0.w);
            As[nb][lk + 4][lm] = totf32(pa1.x); As[nb][lk + 5][lm] = totf32(pa1.y);
            As[nb][lk + 6][lm] = totf32(pa1.z); As[nb][lk + 7][lm] = totf32(pa1.w);
            float4 c0 = make_float4(totf32(pb0.x), totf32(pb0.y), totf32(pb0.z), totf32(pb0.w));
            float4 c1 = make_float4(totf32(pb1.x), totf32(pb1.y), totf32(pb1.z), totf32(pb1.w));
            *(float4*)&Bs[nb][lkb][ln]     = c0;
            *(float4*)&Bs[nb][lkb + 8][ln] = c1;
            __syncthreads();
        }
    }

#pragma unroll
    for (int ni = 0; ni < 4; ni++) {
        const int ncol = n0 + wn + ni * 8 + tg * 2;
#pragma unroll
        for (int mi = 0; mi < 4; mi++) {
            const float* c = acc[mi * 4 + ni];
            const int mr0 = m0 + wm + mi * 16 + gq;
            float2 e0 = *(const float2*)&E[(size_t)mr0 * N + ncol];
            float2 e1 = *(const float2*)&E[(size_t)(mr0 + 8) * N + ncol];
            *(float2*)&C[(size_t)mr0 * N + ncol] =
                make_float2(c[0] + e0.x, c[1] + e0.y);
            *(float2*)&C[(size_t)(mr0 + 8) * N + ncol] =
                make_float2(c[2] + e1.x, c[3] + e1.y);
        }
    }
}

// ================= persistent tensor-core LSTM v2 =================
// 128 blocks = 2 batch-halves (mh) x 64 unit-slices (8 units = 32 gate-cols).
// h ping-pong stored pre-rounded to tf32 -> staging is a pure cp.async copy.
// Ws k-permuted so bf = 2x LDS.64. Scattered g_H stores overlap the barrier.
#define AH_STRIDE 72
#define WS_STRIDE 520
#define SM_FLOATS (HDIM * AH_STRIDE + 32 * WS_STRIDE)
__global__ __launch_bounds__(256, 1) void lstm_tensor2(const float* __restrict__ W_hh)
{
    extern __shared__ float sm[];
    float* Ah = sm;                          // [512][72]  h tile (tf32)
    float* Ws = sm + HDIM * AH_STRIDE;       // [32][520]  W slice (tf32, k-permuted)

    const int tid = threadIdx.x;
    const int lane = tid & 31, w = tid >> 5;
    const int gq = lane >> 2, tg = lane & 3;
    const int mt = w & 3, nh = w >> 2;       // m-tile (16 rows), n-half (16 cols)
    const int mh = blockIdx.x & 1, nb = blockIdx.x >> 1;
    const int u0 = nb * 8;
    const int mrow0 = mh * 64 + mt * 16;

    // ---- one-time: stage W slice as TF32, k-permuted within 8-blocks:
    // element (col j, k) at j*520 + (k>>3)*8 + (k&3)*2 + ((k>>2)&1)
    for (int i = tid; i < 32 * 128; i += 256) {
        const int j = i >> 7, k4 = (i & 127) * 4;
        const int unit = u0 + (j >> 2), gate = j & 3;
        float4 wv = *(const float4*)(W_hh + (size_t)(gate * HDIM + unit) * HDIM + k4);
        float vv[4] = {wv.x, wv.y, wv.z, wv.w};
#pragma unroll
        for (int e = 0; e < 4; e++) {
            const int k = k4 + e;
            Ws[j * WS_STRIDE + ((k >> 3) << 3) + ((k & 3) << 1) + ((k >> 2) & 1)] = totf32(vv[e]);
        }
    }

    // ---- one-time: zero h0 ping buffer (mh==0 blocks cover all units)
    if (mh == 0) {
        for (int i = tid; i < 8 * B_; i += 256)
            g_hT[(u0 + (i >> 7)) * B_ + (i & 127)] = 0.f;
    }

    float cst[2] = {0.f, 0.f};

    __threadfence();
    __syncthreads();
    if (tid == 0) {
        volatile unsigned* genp = &g_barg;
        unsigned g = *genp;
        if (atomicAdd(&g_barc, 1) == 127) {
            g_barc = 0; __threadfence();
            atomicExch((unsigned*)&g_barg, g + 1);
        } else { while (*genp == g) { } }
        __threadfence();
    }
    __syncthreads();

    const int gA = (tg & 1) ? 2 : 0;

    for (int t = 0; t < SDEC; t++) {
        const int cur = t & 1, nxt = cur ^ 1;

        // ---- stage h half [512 u][64 b] via cp.async (pure copy; pre-rounded tf32)
        {
            const float* src = g_hT + cur * (HDIM * B_) + mh * 64;
            for (int i = tid; i < HDIM * 16; i += 256) {
                const int row = i >> 4, seg = (i & 15) * 4;
                cp16(Ah + row * AH_STRIDE + seg, src + (size_t)row * B_ + seg);
            }
            asm volatile("cp.async.commit_group;");
        }

        // ---- prefetch x-part of gates (overlaps cp.async fill)
        float xg[2][4];
#pragma unroll
        for (int ni = 0; ni < 2; ni++) {
            const int u = u0 + nh * 4 + ni * 2 + (tg >> 1);
            const int cA = gA * HDIM + u, cB = cA + HDIM;
            const size_t r0 = ((size_t)t * B_ + mrow0 + gq) * G4H;
            const size_t r1 = r0 + (size_t)8 * G4H;
            xg[ni][0] = __ldg(&g_xWt[r0 + cA]);
            xg[ni][1] = __ldg(&g_xWt[r0 + cB]);
            xg[ni][2] = __ldg(&g_xWt[r1 + cA]);
            xg[ni][3] = __ldg(&g_xWt[r1 + cB]);
        }

        asm volatile("cp.async.wait_group 0;");
        __syncthreads();

        // ---- mma mainloop: 64 k-steps, dual accumulator chains
        float accA[2][4] = {{0,0,0,0},{0,0,0,0}};
        float accB[2][4] = {{0,0,0,0},{0,0,0,0}};
#pragma unroll 4
        for (int kk = 0; kk < 64; kk++) {
            const int k0 = kk * 8;
            u32 af[4];
            af[0] = __float_as_uint(Ah[(k0 + tg    ) * AH_STRIDE + mt * 16 + gq]);
            af[1] = __float_as_uint(Ah[(k0 + tg    ) * AH_STRIDE + mt * 16 + gq + 8]);
            af[2] = __float_as_uint(Ah[(k0 + tg + 4) * AH_STRIDE + mt * 16 + gq]);
            af[3] = __float_as_uint(Ah[(k0 + tg + 4) * AH_STRIDE + mt * 16 + gq + 8]);
            // bf pairs: (k0+tg, k0+tg+4) contiguous in permuted Ws
            float2 b0 = *(const float2*)&Ws[(nh * 16 + gq    ) * WS_STRIDE + k0 + tg * 2];
            float2 b1 = *(const float2*)&Ws[(nh * 16 + 8 + gq) * WS_STRIDE + k0 + tg * 2];
            u32 bf0[2] = {__float_as_uint(b0.x), __float_as_uint(b0.y)};
            u32 bf1[2] = {__float_as_uint(b1.x), __float_as_uint(b1.y)};
            if (kk & 1) { mma_tf32(accB[0], af, bf0); mma_tf32(accB[1], af, bf1); }
            else        { mma_tf32(accA[0], af, bf0); mma_tf32(accA[1], af, bf1); }
        }

        // ---- epilogue: gates -> shuffle -> cell update
        float hsv[2];
        int usv[2], bsv[2];
#pragma unroll
        for (int ni = 0; ni < 2; ni++) {
            float v0 = accA[ni][0] + accB[ni][0] + xg[ni][0];
            float v1 = accA[ni][1] + accB[ni][1] + xg[ni][1];
            float v2 = accA[ni][2] + accB[ni][2] + xg[ni][2];
            float v3 = accA[ni][3] + accB[ni][3] + xg[ni][3];
            float r0 = __shfl_xor_sync(0xffffffffu, v0, 1);
            float r1 = __shfl_xor_sync(0xffffffffu, v1, 1);
            float r2 = __shfl_xor_sync(0xffffffffu, v2, 1);
            float r3 = __shfl_xor_sync(0xffffffffu, v3, 1);
            float iv, fv, gv, ov; int b;
            if (tg & 1) { iv = r2; fv = r3; gv = v2; ov = v3; b = mrow0 + gq + 8; }
            else        { iv = v0; fv = v1; gv = r0; ov = r1; b = mrow0 + gq; }
            float c = sigmoidf_(fv) * cst[ni] + sigmoidf_(iv) * tanhf(gv);
            cst[ni] = c;
            float h = sigmoidf_(ov) * tanhf(c);
            const int u = u0 + nh * 4 + ni * 2 + (tg >> 1);
            // publish tf32-rounded h for next step's staging (rna here == rna at stage)
            g_hT[nxt * (HDIM * B_) + u * B_ + b] = totf32(h);
            hsv[ni] = h; usv[ni] = u; bsv[ni] = b;
        }

        // ---- publish, arrive, overlap scattered history stores with the wait
        __threadfence();
        __syncthreads();
        unsigned mygen = 0; bool rel = false;
        if (tid == 0) {
            volatile unsigned* genp = &g_barg;
            mygen = *genp;
            if (atomicAdd(&g_barc, 1) == 127) {
                g_barc = 0; __threadfence();
                atomicExch((unsigned*)&g_barg, mygen + 1);
                rel = true;
            }
        }
#pragma unroll
        for (int ni = 0; ni < 2; ni++)
            g_H[((size_t)bsv[ni] * SDEC + t) * HDIM + usv[ni]] = hsv[ni];
        if (tid == 0 && !rel) {
            volatile unsigned* genp = &g_barg;
            while (*genp == mygen) { }
            __threadfence();
        }
        __syncthreads();
    }
}

// ---------------- softmax over last dim (256) ----------------
__global__ __launch_bounds__(256) void softmax256(float* __restrict__ S) {
    __shared__ float red[256];
    const int t = threadIdx.x;
    float* p = S + (size_t)blockIdx.x * SENC;
    float v = p[t];
    red[t] = v; __syncthreads();
    for (int s = 128; s > 0; s >>= 1) { if (t < s) red[t] = fmaxf(red[t], red[t + s]); __syncthreads(); }
    float mx = red[0]; __syncthreads();
    float e = __expf(v - mx);
    red[t] = e; __syncthreads();
    for (int s = 128; s > 0; s >>= 1) { if (t < s) red[t] += red[t + s]; __syncthreads(); }
    p[t] = e * (1.0f / red[0]);
}

// ---------------- host ----------------
extern "C" void kernel_launch(void* const* d_in, const int* in_sizes, int n_in,
                              void* d_out, int out_size) {
    const float* x    = (const float*)d_in[0];
    const float* enc  = (const float*)d_in[1];
    const float* W_ih = (const float*)d_in[2];
    const float* W_hh = (const float*)d_in[3];
    const float* b_ih = (const float*)d_in[4];
    const float* b_hh = (const float*)d_in[5];
    const float* Wq   = (const float*)d_in[6];
    const float* bq   = (const float*)d_in[7];
    const float* Wk   = (const float*)d_in[8];
    const float* bk   = (const float*)d_in[9];
    const float* Wv   = (const float*)d_in[10];
    const float* bv   = (const float*)d_in[11];
    const float* Wfc  = (const float*)d_in[12];
    const float* bfc  = (const float*)d_in[13];
    float* out = (float*)d_out;

    float *p_xWt, *p_K, *p_V, *p_H, *p_Q, *p_HC, *p_S, *p_bsum;
    cudaGetSymbolAddress((void**)&p_xWt, g_xWt);
    cudaGetSymbolAddress((void**)&p_K,   g_K);
    cudaGetSymbolAddress((void**)&p_V,   g_V);
    cudaGetSymbolAddress((void**)&p_H,   g_H);
    cudaGetSymbolAddress((void**)&p_Q,   g_Q);
    cudaGetSymbolAddress((void**)&p_HC,  g_HC);
    cudaGetSymbolAddress((void**)&p_S,   g_S);
    cudaGetSymbolAddress((void**)&p_bsum,g_bsum);

    const float scale = 1.0f / sqrtf((float)HDIM);

    cudaFuncSetAttribute(lstm_tensor2,
                         cudaFuncAttributeMaxDynamicSharedMemorySize,
                         SM_FLOATS * sizeof(float));

    bias_sum_kernel<<<G4H / 256, 256>>>(b_ih, b_hh);

    // xW = x @ W_ih^T + (b_ih+b_hh), written transposed to [t][b][col]
    gemm_nt_tf32<<<dim3(G4H / 128, MROWS / 128, 1), 256>>>(
        x, W_ih, p_bsum, p_xWt, MROWS, G4H, IDIM, 1.0f, 0, 0, 0, 1);
    // K = enc @ Wk^T + bk
    gemm_nt_tf32<<<dim3(HDIM / 128, MROWS / 128, 1), 256>>>(
        enc, Wk, bk, p_K, MROWS, HDIM, HDIM, 1.0f, 0, 0, 0, 0);
    // V = K @ Wv^T + bv
    gemm_nt_tf32<<<dim3(HDIM / 128, MROWS / 128, 1), 256>>>(
        p_K, Wv, bv, p_V, MROWS, HDIM, HDIM, 1.0f, 0, 0, 0, 0);

    // entire sequential LSTM in one persistent tensor-core launch
    lstm_tensor2<<<128, 256, SM_FLOATS * sizeof(float)>>>(W_hh);

    // Q = H @ Wq^T + bq
    gemm_nt_tf32<<<dim3(HDIM / 128, MROWS / 128, 1), 256>>>(
        p_H, Wq, bq, p_Q, MROWS, HDIM, HDIM, 1.0f, 0, 0, 0, 0);

    // scores: per-batch S[t,s] = scale * Q[t,:]·K[s,:]
    gemm_nt_tf32<<<dim3(SENC / 128, SDEC / 128, B_), 256>>>(
        p_Q, p_K, nullptr, p_S, SDEC, SENC, HDIM, scale,
        (size_t)SDEC * HDIM, (size_t)SENC * HDIM, (size_t)SDEC * SENC, 0);

    softmax256<<<B_ * SDEC, 256>>>(p_S);

    // context + h: HC[t,h] = sum_s S[t,s] * V[s,h] + H[t,h]
    gemm_nn_addE_tf32<<<dim3(HDIM / 128, SDEC / 128, B_), 256>>>(
        p_S, p_V, p_H, p_HC, SDEC, HDIM, SENC,
        (size_t)SDEC * SENC, (size_t)SENC * HDIM,
        (size_t)SDEC * HDIM, (size_t)SDEC * HDIM);

    // out = HC @ Wfc^T + bfc
    gemm_nt_tf32<<<dim3(ODIM / 128, MROWS / 128, 1), 256>>>(
        p_HC, Wfc, bfc, out, MROWS, ODIM, HDIM, 1.0f, 0, 0, 0, 0);
}

// round 9
// speedup vs baseline: 3.1904x; 1.0678x over previous
#include <cuda_runtime.h>
#include <math.h>

#define B_    128
#define SDEC  256
#define SENC  256
#define IDIM  256
#define HDIM  512
#define ODIM  256
#define G4H   2048
#define MROWS 32768   // B_*SDEC == B_*SENC

typedef unsigned long long ull;
typedef unsigned int u32;

// ---------------- scratch (device globals; no allocs allowed) ----------------
__device__ float g_xW [(size_t)MROWS * G4H];  // x@W_ih^T + biases, [m=b*256+t][col]
__device__ float g_xWf[(size_t)MROWS * G4H];  // fragment layout [t][blk][w][ni][lane][j]
__device__ float g_K [(size_t)MROWS * HDIM];  // enc@Wk^T + bk
__device__ float g_V [(size_t)MROWS * HDIM];  // K@Wv^T + bv
__device__ float g_H [(size_t)MROWS * HDIM];  // all h_t  [b*256+t][u]
__device__ float g_Q [(size_t)MROWS * HDIM];  // H@Wq^T + bq
__device__ float g_HC[(size_t)MROWS * HDIM];  // h + context
__device__ float g_S [(size_t)B_ * SDEC * SENC]; // attention probs
__device__ float g_hT[2 * HDIM * B_];         // h ping-pong [pp][u][b], tf32-rounded
__device__ float g_bsum[G4H];
__device__ unsigned g_barc2[2];
__device__ unsigned g_barg2[2];

__device__ __forceinline__ float sigmoidf_(float x) { return 1.0f / (1.0f + __expf(-x)); }

__device__ __forceinline__ float totf32(float x) {
    u32 r;
    asm("cvt.rna.tf32.f32 %0, %1;" : "=r"(r) : "f"(x));
    return __uint_as_float(r);
}
__device__ __forceinline__ void mma_tf32(float* c, const u32* a, const u32* b) {
    asm("mma.sync.aligned.m16n8k8.row.col.f32.tf32.tf32.f32 "
        "{%0,%1,%2,%3},{%4,%5,%6,%7},{%8,%9},{%0,%1,%2,%3};"
        : "+f"(c[0]), "+f"(c[1]), "+f"(c[2]), "+f"(c[3])
        : "r"(a[0]), "r"(a[1]), "r"(a[2]), "r"(a[3]), "r"(b[0]), "r"(b[1]));
}
__device__ __forceinline__ void cp16(float* dst_smem, const float* src) {
    u32 d = (u32)__cvta_generic_to_shared(dst_smem);
    asm volatile("cp.async.cg.shared.global [%0], [%1], 16;" :: "r"(d), "l"(src));
}

// ---------------- bias sum ----------------
__global__ void bias_sum_kernel(const float* __restrict__ b_ih, const float* __restrict__ b_hh) {
    int i = blockIdx.x * 256 + threadIdx.x;
    if (i < G4H) g_bsum[i] = b_ih[i] + b_hh[i];
}

// ---------------- xW repack: [m=b*256+t][col] -> fragment layout --------------
// dst flat = ((t*128 + blk)*16 + w*2 + ni)*128 + lane*4 + j with
//   blk = nb*2 + mh,  nb = unit>>3,  mh = b>>6
//   w: mt = (b>>4)&3, nh = (unit&7)>>2
//   lane = gq*4 + tg: gq = b&7, tg = (tg>>1 part = (unit>>0)&1 via ni..) see below
//   j = (gate&1) + 2*((b>>3)&1)
// Block = (ug: 16-unit group, t). smem tile [128 b][4 gate][16 du], stride 68.
__global__ __launch_bounds__(256) void repack_xw() {
    __shared__ float sm[128 * 68];
    const int ug = blockIdx.x;      // 0..31
    const int t  = blockIdx.y;      // 0..255
    const int tid = threadIdx.x;

    // load: 2048 float4s, fully coalesced-ish (64B runs)
#pragma unroll
    for (int p = 0; p < 8; p++) {
        const int i = tid + p * 256;        // 0..2047
        const int b = i >> 4, rem = i & 15;
        const int gate = rem >> 2, du4 = rem & 3;
        float4 v = *(const float4*)&g_xW[((size_t)b * SDEC + t) * G4H +
                                         gate * HDIM + ug * 16 + du4 * 4];
        *(float4*)&sm[b * 68 + gate * 16 + du4 * 4] = v;
    }
    __syncthreads();

    // write: 2048 float4s to fragment layout, fully coalesced
#pragma unroll
    for (int p = 0; p < 8; p++) {
        const int e4 = tid + p * 256;       // 0..2047
        const int blkSel = e4 >> 9;         // 0..3
        const int nbL = blkSel >> 1, mh = blkSel & 1;
        const int ew = e4 & 511;
        const int w = ew >> 6, ni = (ew >> 5) & 1, lane = ew & 31;
        const int gq = lane >> 2, tg = lane & 3;
        const int blk = (2 * ug + nbL) * 2 + mh;
        float v[4];
#pragma unroll
        for (int j = 0; j < 4; j++) {
            const int b = mh * 64 + (w & 3) * 16 + (j >> 1) * 8 + gq;
            const int gate = (tg & 1) * 2 + (j & 1);
            const int du = nbL * 8 + (w >> 2) * 4 + ni * 2 + (tg >> 1);
            v[j] = sm[b * 68 + gate * 16 + du];
        }
        *(float4*)&g_xWf[(((size_t)t * 128 + blk) * 16 + w * 2 + ni) * 128 + lane * 4] =
            make_float4(v[0], v[1], v[2], v[3]);
    }
}

// ================= TF32 NT GEMM (unchanged numerics) =================
#define KTILE 16
__global__ __launch_bounds__(256) void gemm_nt_tf32(
    const float* __restrict__ A, const float* __restrict__ B,
    const float* __restrict__ bias, float* __restrict__ C,
    int M, int N, int K, float alpha,
    size_t sA, size_t sB, size_t sC)
{
    __shared__ float As[2][KTILE][136];
    __shared__ float Bs[2][KTILE][136];

    const int z = blockIdx.z;
    A += (size_t)z * sA; B += (size_t)z * sB; C += (size_t)z * sC;

    const int tid = threadIdx.x;
    const int m0 = blockIdx.y * 128, n0 = blockIdx.x * 128;
    const int w = tid >> 5, lane = tid & 31;
    const int wm = (w >> 2) * 64, wn = (w & 3) * 32;
    const int gq = lane >> 2, tg = lane & 3;

    const int lm = tid & 127;
    const int lk = (tid >> 7) * 8;
    const float* Ag = A + (size_t)(m0 + lm) * K + lk;
    const float* Bg = B + (size_t)(n0 + lm) * K + lk;

    float acc[16][4];
#pragma unroll
    for (int i = 0; i < 16; i++)
#pragma unroll
        for (int j = 0; j < 4; j++) acc[i][j] = 0.f;

    float4 pa0 = *(const float4*)(Ag);
    float4 pa1 = *(const float4*)(Ag + 4);
    float4 pb0 = *(const float4*)(Bg);
    float4 pb1 = *(const float4*)(Bg + 4);
    {
        As[0][lk + 0][lm] = totf32(pa0.x); As[0][lk + 1][lm] = totf32(pa0.y);
        As[0][lk + 2][lm] = totf32(pa0.z); As[0][lk + 3][lm] = totf32(pa0.w);
        As[0][lk + 4][lm] = totf32(pa1.x); As[0][lk + 5][lm] = totf32(pa1.y);
        As[0][lk + 6][lm] = totf32(pa1.z); As[0][lk + 7][lm] = totf32(pa1.w);
        Bs[0][lk + 0][lm] = totf32(pb0.x); Bs[0][lk + 1][lm] = totf32(pb0.y);
        Bs[0][lk + 2][lm] = totf32(pb0.z); Bs[0][lk + 3][lm] = totf32(pb0.w);
        Bs[0][lk + 4][lm] = totf32(pb1.x); Bs[0][lk + 5][lm] = totf32(pb1.y);
        Bs[0][lk + 6][lm] = totf32(pb1.z); Bs[0][lk + 7][lm] = totf32(pb1.w);
    }
    __syncthreads();

    const int KTiles = K / KTILE;
    for (int kt = 0; kt < KTiles; kt++) {
        const int cur = kt & 1;
        const bool has = (kt + 1 < KTiles);
        if (has) {
            pa0 = *(const float4*)(Ag + (kt + 1) * KTILE);
            pa1 = *(const float4*)(Ag + (kt + 1) * KTILE + 4);
            pb0 = *(const float4*)(Bg + (kt + 1) * KTILE);
            pb1 = *(const float4*)(Bg + (kt + 1) * KTILE + 4);
        }
#pragma unroll
        for (int kk = 0; kk < 2; kk++) {
            const int kb = kk * 8;
            u32 af[4][4], bf[4][2];
#pragma unroll
            for (int mi = 0; mi < 4; mi++) {
                af[mi][0] = __float_as_uint(As[cur][kb + tg    ][wm + mi * 16 + gq]);
                af[mi][1] = __float_as_uint(As[cur][kb + tg    ][wm + mi * 16 + gq + 8]);
                af[mi][2] = __float_as_uint(As[cur][kb + tg + 4][wm + mi * 16 + gq]);
                af[mi][3] = __float_as_uint(As[cur][kb + tg + 4][wm + mi * 16 + gq + 8]);
            }
#pragma unroll
            for (int ni = 0; ni < 4; ni++) {
                bf[ni][0] = __float_as_uint(Bs[cur][kb + tg    ][wn + ni * 8 + gq]);
                bf[ni][1] = __float_as_uint(Bs[cur][kb + tg + 4][wn + ni * 8 + gq]);
            }
#pragma unroll
            for (int mi = 0; mi < 4; mi++)
#pragma unroll
                for (int ni = 0; ni < 4; ni++)
                    mma_tf32(acc[mi * 4 + ni], af[mi], bf[ni]);
        }
        if (has) {
            const int nb = cur ^ 1;
            As[nb][lk + 0][lm] = totf32(pa0.x); As[nb][lk + 1][lm] = totf32(pa0.y);
            As[nb][lk + 2][lm] = totf32(pa0.z); As[nb][lk + 3][lm] = totf32(pa0.w);
            As[nb][lk + 4][lm] = totf32(pa1.x); As[nb][lk + 5][lm] = totf32(pa1.y);
            As[nb][lk + 6][lm] = totf32(pa1.z); As[nb][lk + 7][lm] = totf32(pa1.w);
            Bs[nb][lk + 0][lm] = totf32(pb0.x); Bs[nb][lk + 1][lm] = totf32(pb0.y);
            Bs[nb][lk + 2][lm] = totf32(pb0.z); Bs[nb][lk + 3][lm] = totf32(pb0.w);
            Bs[nb][lk + 4][lm] = totf32(pb1.x); Bs[nb][lk + 5][lm] = totf32(pb1.y);
            Bs[nb][lk + 6][lm] = totf32(pb1.z); Bs[nb][lk + 7][lm] = totf32(pb1.w);
            __syncthreads();
        }
    }

#pragma unroll
    for (int ni = 0; ni < 4; ni++) {
        const int ncol = n0 + wn + ni * 8 + tg * 2;
        float2 bv = make_float2(0.f, 0.f);
        if (bias) bv = *(const float2*)&bias[ncol];
#pragma unroll
        for (int mi = 0; mi < 4; mi++) {
            const float* c = acc[mi * 4 + ni];
            const int mr0 = m0 + wm + mi * 16 + gq;
            float2 lo = make_float2(alpha * c[0] + bv.x, alpha * c[1] + bv.y);
            float2 hi = make_float2(alpha * c[2] + bv.x, alpha * c[3] + bv.y);
            *(float2*)&C[(size_t)mr0 * N + ncol]       = lo;
            *(float2*)&C[(size_t)(mr0 + 8) * N + ncol] = hi;
        }
    }
}

// ================= TF32 NN GEMM + E add (unchanged) =================
__global__ __launch_bounds__(256) void gemm_nn_addE_tf32(
    const float* __restrict__ A, const float* __restrict__ B,
    const float* __restrict__ E, float* __restrict__ C,
    int M, int N, int K,
    size_t sA, size_t sB, size_t sE, size_t sC)
{
    __shared__ float As[2][KTILE][136];
    __shared__ float Bs[2][KTILE][136];

    const int z = blockIdx.z;
    A += (size_t)z * sA; B += (size_t)z * sB; E += (size_t)z * sE; C += (size_t)z * sC;

    const int tid = threadIdx.x;
    const int m0 = blockIdx.y * 128, n0 = blockIdx.x * 128;
    const int w = tid >> 5, lane = tid & 31;
    const int wm = (w >> 2) * 64, wn = (w & 3) * 32;
    const int gq = lane >> 2, tg = lane & 3;

    const int lm = tid & 127;
    const int lk = (tid >> 7) * 8;
    const float* Ag = A + (size_t)(m0 + lm) * K + lk;
    const int ln  = lane * 4;
    const int lkb = w;
    const float* Bg = B + (size_t)lkb * N + n0 + ln;

    float acc[16][4];
#pragma unroll
    for (int i = 0; i < 16; i++)
#pragma unroll
        for (int j = 0; j < 4; j++) acc[i][j] = 0.f;

    float4 pa0 = *(const float4*)(Ag);
    float4 pa1 = *(const float4*)(Ag + 4);
    float4 pb0 = *(const float4*)(Bg);
    float4 pb1 = *(const float4*)(Bg + (size_t)8 * N);
    {
        As[0][lk + 0][lm] = totf32(pa0.x); As[0][lk + 1][lm] = totf32(pa0.y);
        As[0][lk + 2][lm] = totf32(pa0.z); As[0][lk + 3][lm] = totf32(pa0.w);
        As[0][lk + 4][lm] = totf32(pa1.x); As[0][lk + 5][lm] = totf32(pa1.y);
        As[0][lk + 6][lm] = totf32(pa1.z); As[0][lk + 7][lm] = totf32(pa1.w);
        float4 c0 = make_float4(totf32(pb0.x), totf32(pb0.y), totf32(pb0.z), totf32(pb0.w));
        float4 c1 = make_float4(totf32(pb1.x), totf32(pb1.y), totf32(pb1.z), totf32(pb1.w));
        *(float4*)&Bs[0][lkb][ln]     = c0;
        *(float4*)&Bs[0][lkb + 8][ln] = c1;
    }
    __syncthreads();

    const int KTiles = K / KTILE;
    for (int kt = 0; kt < KTiles; kt++) {
        const int cur = kt & 1;
        const bool has = (kt + 1 < KTiles);
        if (has) {
            pa0 = *(const float4*)(Ag + (kt + 1) * KTILE);
            pa1 = *(const float4*)(Ag + (kt + 1) * KTILE + 4);
            pb0 = *(const float4*)(Bg + (size_t)((kt + 1) * KTILE) * N);
            pb1 = *(const float4*)(Bg + (size_t)((kt + 1) * KTILE + 8) * N);
        }
#pragma unroll
        for (int kk = 0; kk < 2; kk++) {
            const int kb = kk * 8;
            u32 af[4][4], bf[4][2];
#pragma unroll
            for (int mi = 0; mi < 4; mi++) {
                af[mi][0] = __float_as_uint(As[cur][kb + tg    ][wm + mi * 16 + gq]);
                af[mi][1] = __float_as_uint(As[cur][kb + tg    ][wm + mi * 16 + gq + 8]);
                af[mi][2] = __float_as_uint(As[cur][kb + tg + 4][wm + mi * 16 + gq]);
                af[mi][3] = __float_as_uint(As[cur][kb + tg + 4][wm + mi * 16 + gq + 8]);
            }
#pragma unroll
            for (int ni = 0; ni < 4; ni++) {
                bf[ni][0] = __float_as_uint(Bs[cur][kb + tg    ][wn + ni * 8 + gq]);
                bf[ni][1] = __float_as_uint(Bs[cur][kb + tg + 4][wn + ni * 8 + gq]);
            }
#pragma unroll
            for (int mi = 0; mi < 4; mi++)
#pragma unroll
                for (int ni = 0; ni < 4; ni++)
                    mma_tf32(acc[mi * 4 + ni], af[mi], bf[ni]);
        }
        if (has) {
            const int nb = cur ^ 1;
            As[nb][lk + 0][lm] = totf32(pa0.x); As[nb][lk + 1][lm] = totf32(pa0.y);
            As[nb][lk + 2][lm] = totf32(pa0.z); As[nb][lk + 3][lm] = totf32(pa0.w);
            As[nb][lk + 4][lm] = totf32(pa1.x); As[nb][lk + 5][lm] = totf32(pa1.y);
            As[nb][lk + 6][lm] = totf32(pa1.z); As[nb][lk + 7][lm] = totf32(pa1.w);
            float4 c0 = make_float4(totf32(pb0.x), totf32(pb0.y), totf32(pb0.z), totf32(pb0.w));
            float4 c1 = make_float4(totf32(pb1.x), totf32(pb1.y), totf32(pb1.z), totf32(pb1.w));
            *(float4*)&Bs[nb][lkb][ln]     = c0;
            *(float4*)&Bs[nb][lkb + 8][ln] = c1;
            __syncthreads();
        }
    }

#pragma unroll
    for (int ni = 0; ni < 4; ni++) {
        const int ncol = n0 + wn + ni * 8 + tg * 2;
#pragma unroll
        for (int mi = 0; mi < 4; mi++) {
            const float* c = acc[mi * 4 + ni];
            const int mr0 = m0 + wm + mi * 16 + gq;
            float2 e0 = *(const float2*)&E[(size_t)mr0 * N + ncol];
            float2 e1 = *(const float2*)&E[(size_t)(mr0 + 8) * N + ncol];
            *(float2*)&C[(size_t)mr0 * N + ncol] =
                make_float2(c[0] + e0.x, c[1] + e0.y);
            *(float2*)&C[(size_t)(mr0 + 8) * N + ncol] =
                make_float2(c[2] + e1.x, c[3] + e1.y);
        }
    }
}

// ================= persistent tensor-core LSTM v3 =================
// Per-mh barriers (64 blocks each), coalesced fragment-layout xg loads,
// 2-group pipelined cp.async h staging.
#define AH_STRIDE 72
#define WS_STRIDE 520
#define SM_FLOATS (HDIM * AH_STRIDE + 32 * WS_STRIDE)
__global__ __launch_bounds__(256, 1) void lstm_tensor3(const float* __restrict__ W_hh)
{
    extern __shared__ float sm[];
    float* Ah = sm;                          // [512][72]  h tile (tf32)
    float* Ws = sm + HDIM * AH_STRIDE;       // [32][520]  W slice (tf32, k-permuted)

    const int tid = threadIdx.x;
    const int lane = tid & 31, w = tid >> 5;
    const int gq = lane >> 2, tg = lane & 3;
    const int mt = w & 3, nh = w >> 2;
    const int mh = blockIdx.x & 1, nb = blockIdx.x >> 1;
    const int u0 = nb * 8;
    const int mrow0 = mh * 64 + mt * 16;

    // ---- one-time: stage W slice as TF32, k-permuted within 8-blocks
    for (int i = tid; i < 32 * 128; i += 256) {
        const int j = i >> 7, k4 = (i & 127) * 4;
        const int unit = u0 + (j >> 2), gate = j & 3;
        float4 wv = *(const float4*)(W_hh + (size_t)(gate * HDIM + unit) * HDIM + k4);
        float vv[4] = {wv.x, wv.y, wv.z, wv.w};
#pragma unroll
        for (int e = 0; e < 4; e++) {
            const int k = k4 + e;
            Ws[j * WS_STRIDE + ((k >> 3) << 3) + ((k & 3) << 1) + ((k >> 2) & 1)] = totf32(vv[e]);
        }
    }

    // ---- one-time: zero own slice of h0 ping buffer (units u0..u0+7, mh half)
    for (int i = tid; i < 8 * 64; i += 256)
        g_hT[(u0 + (i >> 6)) * B_ + mh * 64 + (i & 63)] = 0.f;

    float cst[2] = {0.f, 0.f};

    __threadfence();
    __syncthreads();
    if (tid == 0) {
        volatile unsigned* genp = &g_barg2[mh];
        unsigned g = *genp;
        if (atomicAdd(&g_barc2[mh], 1) == 63) {
            g_barc2[mh] = 0; __threadfence();
            atomicExch((unsigned*)&g_barg2[mh], g + 1);
        } else { while (*genp == g) { } }
        __threadfence();
    }
    __syncthreads();

    for (int t = 0; t < SDEC; t++) {
        const int cur = t & 1, nxt = cur ^ 1;

        // ---- stage h half [512 u][64 b] via cp.async, two pipelined groups
        const float* src = g_hT + cur * (HDIM * B_) + mh * 64;
        {
#pragma unroll
            for (int p = 0; p < 16; p++) {
                const int i = tid + p * 256;
                const int row = i >> 4, seg = (i & 15) * 4;
                cp16(Ah + row * AH_STRIDE + seg, src + (size_t)row * B_ + seg);
            }
            asm volatile("cp.async.commit_group;");
#pragma unroll
            for (int p = 16; p < 32; p++) {
                const int i = tid + p * 256;
                const int row = i >> 4, seg = (i & 15) * 4;
                cp16(Ah + row * AH_STRIDE + seg, src + (size_t)row * B_ + seg);
            }
            asm volatile("cp.async.commit_group;");
        }

        // ---- coalesced fragment-layout x-gate loads (2x LDG.128)
        float xg[2][4];
        {
            const float* xb = g_xWf + (((size_t)t * 128 + blockIdx.x) * 16 + w * 2) * 128;
            float4 xv0 = __ldg((const float4*)(xb + lane * 4));
            float4 xv1 = __ldg((const float4*)(xb + 128 + lane * 4));
            xg[0][0] = xv0.x; xg[0][1] = xv0.y; xg[0][2] = xv0.z; xg[0][3] = xv0.w;
            xg[1][0] = xv1.x; xg[1][1] = xv1.y; xg[1][2] = xv1.z; xg[1][3] = xv1.w;
        }

        asm volatile("cp.async.wait_group 1;");
        __syncthreads();

        // ---- mma mainloop part 1 (k 0..255)
        float accA[2][4] = {{0,0,0,0},{0,0,0,0}};
        float accB[2][4] = {{0,0,0,0},{0,0,0,0}};
#pragma unroll 4
        for (int kk = 0; kk < 32; kk++) {
            const int k0 = kk * 8;
            u32 af[4];
            af[0] = __float_as_uint(Ah[(k0 + tg    ) * AH_STRIDE + mt * 16 + gq]);
            af[1] = __float_as_uint(Ah[(k0 + tg    ) * AH_STRIDE + mt * 16 + gq + 8]);
            af[2] = __float_as_uint(Ah[(k0 + tg + 4) * AH_STRIDE + mt * 16 + gq]);
            af[3] = __float_as_uint(Ah[(k0 + tg + 4) * AH_STRIDE + mt * 16 + gq + 8]);
            float2 b0 = *(const float2*)&Ws[(nh * 16 + gq    ) * WS_STRIDE + k0 + tg * 2];
            float2 b1 = *(const float2*)&Ws[(nh * 16 + 8 + gq) * WS_STRIDE + k0 + tg * 2];
            u32 bf0[2] = {__float_as_uint(b0.x), __float_as_uint(b0.y)};
            u32 bf1[2] = {__float_as_uint(b1.x), __float_as_uint(b1.y)};
            if (kk & 1) { mma_tf32(accB[0], af, bf0); mma_tf32(accB[1], af, bf1); }
            else        { mma_tf32(accA[0], af, bf0); mma_tf32(accA[1], af, bf1); }
        }

        asm volatile("cp.async.wait_group 0;");
        __syncthreads();

        // ---- mma mainloop part 2 (k 256..511)
#pragma unroll 4
        for (int kk = 32; kk < 64; kk++) {
            const int k0 = kk * 8;
            u32 af[4];
            af[0] = __float_as_uint(Ah[(k0 + tg    ) * AH_STRIDE + mt * 16 + gq]);
            af[1] = __float_as_uint(Ah[(k0 + tg    ) * AH_STRIDE + mt * 16 + gq + 8]);
            af[2] = __float_as_uint(Ah[(k0 + tg + 4) * AH_STRIDE + mt * 16 + gq]);
            af[3] = __float_as_uint(Ah[(k0 + tg + 4) * AH_STRIDE + mt * 16 + gq + 8]);
            float2 b0 = *(const float2*)&Ws[(nh * 16 + gq    ) * WS_STRIDE + k0 + tg * 2];
            float2 b1 = *(const float2*)&Ws[(nh * 16 + 8 + gq) * WS_STRIDE + k0 + tg * 2];
            u32 bf0[2] = {__float_as_uint(b0.x), __float_as_uint(b0.y)};
            u32 bf1[2] = {__float_as_uint(b1.x), __float_as_uint(b1.y)};
            if (kk & 1) { mma_tf32(accB[0], af, bf0); mma_tf32(accB[1], af, bf1); }
            else        { mma_tf32(accA[0], af, bf0); mma_tf32(accA[1], af, bf1); }
        }

        // ---- epilogue: gates -> shuffle -> cell update
        float hsv[2];
        int usv[2], bsv[2];
#pragma unroll
        for (int ni = 0; ni < 2; ni++) {
            float v0 = accA[ni][0] + accB[ni][0] + xg[ni][0];
            float v1 = accA[ni][1] + accB[ni][1] + xg[ni][1];
            float v2 = accA[ni][2] + accB[ni][2] + xg[ni][2];
            float v3 = accA[ni][3] + accB[ni][3] + xg[ni][3];
            float r0 = __shfl_xor_sync(0xffffffffu, v0, 1);
            float r1 = __shfl_xor_sync(0xffffffffu, v1, 1);
            float r2 = __shfl_xor_sync(0xffffffffu, v2, 1);
            float r3 = __shfl_xor_sync(0xffffffffu, v3, 1);
            float iv, fv, gv, ov; int b;
            if (tg & 1) { iv = r2; fv = r3; gv = v2; ov = v3; b = mrow0 + gq + 8; }
            else        { iv = v0; fv = v1; gv = r0; ov = r1; b = mrow0 + gq; }
            float c = sigmoidf_(fv) * cst[ni] + sigmoidf_(iv) * tanhf(gv);
            cst[ni] = c;
            float h = sigmoidf_(ov) * tanhf(c);
            const int u = u0 + nh * 4 + ni * 2 + (tg >> 1);
            g_hT[nxt * (HDIM * B_) + u * B_ + b] = totf32(h);
            hsv[ni] = h; usv[ni] = u; bsv[ni] = b;
        }

        // ---- publish, arrive (per-mh), overlap history stores with the wait
        __threadfence();
        __syncthreads();
        unsigned mygen = 0; bool rel = false;
        if (tid == 0) {
            volatile unsigned* genp = &g_barg2[mh];
            mygen = *genp;
            if (atomicAdd(&g_barc2[mh], 1) == 63) {
                g_barc2[mh] = 0; __threadfence();
                atomicExch((unsigned*)&g_barg2[mh], mygen + 1);
                rel = true;
            }
        }
#pragma unroll
        for (int ni = 0; ni < 2; ni++)
            g_H[((size_t)bsv[ni] * SDEC + t) * HDIM + usv[ni]] = hsv[ni];
        if (tid == 0 && !rel) {
            volatile unsigned* genp = &g_barg2[mh];
            while (*genp == mygen) { }
            __threadfence();
        }
        __syncthreads();
    }
}

// ---------------- softmax over last dim (256) ----------------
__global__ __launch_bounds__(256) void softmax256(float* __restrict__ S) {
    __shared__ float red[256];
    const int t = threadIdx.x;
    float* p = S + (size_t)blockIdx.x * SENC;
    float v = p[t];
    red[t] = v; __syncthreads();
    for (int s = 128; s > 0; s >>= 1) { if (t < s) red[t] = fmaxf(red[t], red[t + s]); __syncthreads(); }
    float mx = red[0]; __syncthreads();
    float e = __expf(v - mx);
    red[t] = e; __syncthreads();
    for (int s = 128; s > 0; s >>= 1) { if (t < s) red[t] += red[t + s]; __syncthreads(); }
    p[t] = e * (1.0f / red[0]);
}

// ---------------- host ----------------
extern "C" void kernel_launch(void* const* d_in, const int* in_sizes, int n_in,
                              void* d_out, int out_size) {
    const float* x    = (const float*)d_in[0];
    const float* enc  = (const float*)d_in[1];
    const float* W_ih = (const float*)d_in[2];
    const float* W_hh = (const float*)d_in[3];
    const float* b_ih = (const float*)d_in[4];
    const float* b_hh = (const float*)d_in[5];
    const float* Wq   = (const float*)d_in[6];
    const float* bq   = (const float*)d_in[7];
    const float* Wk   = (const float*)d_in[8];
    const float* bk   = (const float*)d_in[9];
    const float* Wv   = (const float*)d_in[10];
    const float* bv   = (const float*)d_in[11];
    const float* Wfc  = (const float*)d_in[12];
    const float* bfc  = (const float*)d_in[13];
    float* out = (float*)d_out;

    float *p_xW, *p_K, *p_V, *p_H, *p_Q, *p_HC, *p_S, *p_bsum;
    cudaGetSymbolAddress((void**)&p_xW,  g_xW);
    cudaGetSymbolAddress((void**)&p_K,   g_K);
    cudaGetSymbolAddress((void**)&p_V,   g_V);
    cudaGetSymbolAddress((void**)&p_H,   g_H);
    cudaGetSymbolAddress((void**)&p_Q,   g_Q);
    cudaGetSymbolAddress((void**)&p_HC,  g_HC);
    cudaGetSymbolAddress((void**)&p_S,   g_S);
    cudaGetSymbolAddress((void**)&p_bsum,g_bsum);

    const float scale = 1.0f / sqrtf((float)HDIM);

    cudaFuncSetAttribute(lstm_tensor3,
                         cudaFuncAttributeMaxDynamicSharedMemorySize,
                         SM_FLOATS * sizeof(float));

    bias_sum_kernel<<<G4H / 256, 256>>>(b_ih, b_hh);

    // xW = x @ W_ih^T + (b_ih+b_hh)   [m][col]
    gemm_nt_tf32<<<dim3(G4H / 128, MROWS / 128, 1), 256>>>(
        x, W_ih, p_bsum, p_xW, MROWS, G4H, IDIM, 1.0f, 0, 0, 0);
    // repack to recurrence fragment layout
    repack_xw<<<dim3(32, 256), 256>>>();
    // K = enc @ Wk^T + bk
    gemm_nt_tf32<<<dim3(HDIM / 128, MROWS / 128, 1), 256>>>(
        enc, Wk, bk, p_K, MROWS, HDIM, HDIM, 1.0f, 0, 0, 0);
    // V = K @ Wv^T + bv
    gemm_nt_tf32<<<dim3(HDIM / 128, MROWS / 128, 1), 256>>>(
        p_K, Wv, bv, p_V, MROWS, HDIM, HDIM, 1.0f, 0, 0, 0);

    // entire sequential LSTM in one persistent tensor-core launch
    lstm_tensor3<<<128, 256, SM_FLOATS * sizeof(float)>>>(W_hh);

    // Q = H @ Wq^T + bq
    gemm_nt_tf32<<<dim3(HDIM / 128, MROWS / 128, 1), 256>>>(
        p_H, Wq, bq, p_Q, MROWS, HDIM, HDIM, 1.0f, 0, 0, 0);

    // scores: per-batch S[t,s] = scale * Q[t,:]·K[s,:]
    gemm_nt_tf32<<<dim3(SENC / 128, SDEC / 128, B_), 256>>>(
        p_Q, p_K, nullptr, p_S, SDEC, SENC, HDIM, scale,
        (size_t)SDEC * HDIM, (size_t)SENC * HDIM, (size_t)SDEC * SENC);

    softmax256<<<B_ * SDEC, 256>>>(p_S);

    // context + h: HC[t,h] = sum_s S[t,s] * V[s,h] + H[t,h]
    gemm_nn_addE_tf32<<<dim3(HDIM / 128, SDEC / 128, B_), 256>>>(
        p_S, p_V, p_H, p_HC, SDEC, HDIM, SENC,
        (size_t)SDEC * SENC, (size_t)SENC * HDIM,
        (size_t)SDEC * HDIM, (size_t)SDEC * HDIM);

    // out = HC @ Wfc^T + bfc
    gemm_nt_tf32<<<dim3(ODIM / 128, MROWS / 128, 1), 256>>>(
        p_HC, Wfc, bfc, out, MROWS, ODIM, HDIM, 1.0f, 0, 0, 0);
}